// round 4
// baseline (speedup 1.0000x reference)
#include <cuda_runtime.h>
#include <cuda_bf16.h>
#include <cstdint>
#include <cstdio>

#define T_SEQ   4096
#define D_MODEL 1024
#define NH      16
#define NKV     4
#define HD      64
#define QL      512
#define KVL     256

// ---------------- scratch (device globals; no allocations allowed) ----------
static __device__ int            g_f32flag;                 // 1 = inputs are f32 storage
static __device__ __nv_bfloat16  g_xin   [T_SEQ * D_MODEL];
static __device__ __nv_bfloat16  g_sin   [T_SEQ * HD];
static __device__ __nv_bfloat16  g_cos   [T_SEQ * HD];
static __device__ __nv_bfloat16  g_wdq   [D_MODEL * QL];
static __device__ __nv_bfloat16  g_wuq   [QL * D_MODEL];
static __device__ __nv_bfloat16  g_wdkv  [D_MODEL * KVL];
static __device__ __nv_bfloat16  g_wuk   [KVL * NKV * HD];
static __device__ __nv_bfloat16  g_wuv   [KVL * NKV * HD];
static __device__ __nv_bfloat16  g_wo    [D_MODEL * D_MODEL];

static __device__ __nv_bfloat16 g_qlat_raw[T_SEQ * QL];
static __device__ __nv_bfloat16 g_qlat    [T_SEQ * QL];
static __device__ __nv_bfloat16 g_q       [T_SEQ * NH * HD];
static __device__ __nv_bfloat16 g_q_ro    [T_SEQ * NH * HD];
static __device__ __nv_bfloat16 g_kvraw   [T_SEQ * KVL];
static __device__ __nv_bfloat16 g_kvlat   [T_SEQ * KVL];
static __device__ __nv_bfloat16 g_k       [T_SEQ * NKV * HD];
static __device__ __nv_bfloat16 g_k_ro    [T_SEQ * NKV * HD];
static __device__ __nv_bfloat16 g_v       [T_SEQ * NKV * HD];
static __device__ __nv_bfloat16 g_attn    [T_SEQ * D_MODEL];

// ---------------- dtype detection -------------------------------------------
// If the buffer holds float32 encodings of bf16-valued numbers, the low 16
// mantissa bits of every word are zero. If it holds packed bf16 (N(0,1) data),
// the low 16 bits are a nonzero bf16 value essentially always.
__global__ void detect_kernel(const uint32_t* __restrict__ xw) {
    __shared__ int cnt;
    if (threadIdx.x == 0) cnt = 0;
    __syncthreads();
    uint32_t w = xw[threadIdx.x];          // first 256 words (1 KB) — safe either way
    if ((w & 0xFFFFu) == 0u) atomicAdd(&cnt, 1);
    __syncthreads();
    if (threadIdx.x == 0) {
        g_f32flag = (cnt > 128) ? 1 : 0;
        printf("DIAG f32flag=%d zerolow=%d/256 w0=%08x w1=%08x w2=%08x w3=%08x\n",
               g_f32flag, cnt, xw[0], xw[1], xw[2], xw[3]);
    }
}

// normalize an input buffer into bf16 scratch, honoring the detected dtype
__global__ void convert_kernel(const void* __restrict__ src,
                               __nv_bfloat16* __restrict__ dst, int n) {
    int i = blockIdx.x * blockDim.x + threadIdx.x;
    if (i >= n) return;
    if (g_f32flag)
        dst[i] = __float2bfloat16(((const float*)src)[i]);   // lossless: values are bf16-valued
    else
        dst[i] = ((const __nv_bfloat16*)src)[i];
}

// ---------------- naive GEMM: C[M,N] = A[M,K] @ B[K,N] ----------------------
__global__ void gemm_naive(const __nv_bfloat16* __restrict__ A,
                           const __nv_bfloat16* __restrict__ B,
                           __nv_bfloat16* __restrict__ C,
                           int M, int N, int K) {
    int idx = blockIdx.x * blockDim.x + threadIdx.x;
    if (idx >= M * N) return;
    int m = idx / N;
    int n = idx - m * N;
    const __nv_bfloat16* a = A + (size_t)m * K;
    float acc = 0.0f;
    for (int k = 0; k < K; k++)
        acc = fmaf(__bfloat162float(a[k]),
                   __bfloat162float(B[(size_t)k * N + n]), acc);
    C[idx] = __float2bfloat16(acc);
}

// final GEMM: writes output in the detected dtype (bf16 value either way)
__global__ void gemm_out(const __nv_bfloat16* __restrict__ A,
                         const __nv_bfloat16* __restrict__ B,
                         void* __restrict__ C,
                         int M, int N, int K) {
    int idx = blockIdx.x * blockDim.x + threadIdx.x;
    if (idx >= M * N) return;
    int m = idx / N;
    int n = idx - m * N;
    const __nv_bfloat16* a = A + (size_t)m * K;
    float acc = 0.0f;
    for (int k = 0; k < K; k++)
        acc = fmaf(__bfloat162float(a[k]),
                   __bfloat162float(B[(size_t)k * N + n]), acc);
    __nv_bfloat16 r = __float2bfloat16(acc);
    if (g_f32flag) ((float*)C)[idx] = __bfloat162float(r);
    else           ((__nv_bfloat16*)C)[idx] = r;
}

// ---------------- naive RMSNorm (tree reduction, deterministic) -------------
__global__ void rmsnorm_naive(const __nv_bfloat16* __restrict__ in,
                              const float* __restrict__ scale,
                              __nv_bfloat16* __restrict__ out,
                              int cols) {
    const int row = blockIdx.x;
    const int tid = threadIdx.x;            // 256 threads
    const __nv_bfloat16* x = in + (size_t)row * cols;
    __nv_bfloat16* y = out + (size_t)row * cols;

    __shared__ float red[256];
    float s = 0.0f;
    for (int c = tid; c < cols; c += 256) {
        float v = __bfloat162float(x[c]);
        s += v * v;
    }
    red[tid] = s;
    __syncthreads();
    for (int off = 128; off > 0; off >>= 1) {
        if (tid < off) red[tid] += red[tid + off];
        __syncthreads();
    }
    float inv = 1.0f / sqrtf(red[0] / (float)cols + 1e-6f);
    for (int c = tid; c < cols; c += 256) {
        float v = __bfloat162float(x[c]);
        y[c] = __float2bfloat16(v * inv * scale[c]);
    }
}

// ---------------- RoPE: out = bf16(bf16(x*cos) + bf16(rot*sin)) -------------
__global__ void rope_naive(const __nv_bfloat16* __restrict__ in,
                           const __nv_bfloat16* __restrict__ sin_t,
                           const __nv_bfloat16* __restrict__ cos_t,
                           __nv_bfloat16* __restrict__ out,
                           int heads) {
    int idx = blockIdx.x * blockDim.x + threadIdx.x;
    int total = T_SEQ * heads * HD;
    if (idx >= total) return;

    int d = idx & 63;
    int th = idx >> 6;
    int t = th / heads;

    float xv = __bfloat162float(in[idx]);
    float rot = (d < 32) ? -__bfloat162float(in[idx + 32])
                         :  __bfloat162float(in[idx - 32]);
    float c  = __bfloat162float(cos_t[t * HD + d]);
    float sn = __bfloat162float(sin_t[t * HD + d]);
    float r1 = __bfloat162float(__float2bfloat16(xv * c));
    float r2 = __bfloat162float(__float2bfloat16(rot * sn));
    out[idx] = __float2bfloat16(r1 + r2);
}

// ---------------- naive causal attention -------------------------------------
__global__ void __launch_bounds__(64)
attn_naive(const __nv_bfloat16* __restrict__ Q,
           const __nv_bfloat16* __restrict__ Kc,
           const __nv_bfloat16* __restrict__ Vc,
           __nv_bfloat16* __restrict__ O) {
    const int t  = blockIdx.x;
    const int h  = blockIdx.y;
    const int hk = h >> 2;              // GQA: repeat = NH/NKV = 4
    const int d  = threadIdx.x;         // 0..63

    __shared__ float qs[64];
    __shared__ float red[64];
    __shared__ float sbuf[T_SEQ];

    qs[d] = __bfloat162float(Q[(size_t)t * D_MODEL + h * HD + d]);
    __syncthreads();

    float m = -1e30f;
    for (int j = d; j <= t; j += 64) {
        const __nv_bfloat16* kp = Kc + (size_t)j * (NKV * HD) + hk * HD;
        float acc = 0.0f;
        for (int dd = 0; dd < 64; dd++)
            acc = fmaf(qs[dd], __bfloat162float(kp[dd]), acc);
        float s = __bfloat162float(__float2bfloat16(acc)) * 0.125f;
        sbuf[j] = s;
        m = fmaxf(m, s);
    }
    red[d] = m;
    __syncthreads();
    for (int off = 32; off > 0; off >>= 1) {
        if (d < off) red[d] = fmaxf(red[d], red[d + off]);
        __syncthreads();
    }
    m = red[0];
    __syncthreads();

    float l = 0.0f;
    for (int j = d; j <= t; j += 64)
        l += __expf(sbuf[j] - m);
    red[d] = l;
    __syncthreads();
    for (int off = 32; off > 0; off >>= 1) {
        if (d < off) red[d] += red[d + off];
        __syncthreads();
    }
    const float inv_l = 1.0f / red[0];
    __syncthreads();

    for (int j = d; j <= t; j += 64)
        sbuf[j] = __bfloat162float(__float2bfloat16(__expf(sbuf[j] - m) * inv_l));
    __syncthreads();

    float o = 0.0f;
    for (int j = 0; j <= t; j++)
        o = fmaf(sbuf[j],
                 __bfloat162float(Vc[(size_t)j * (NKV * HD) + hk * HD + d]), o);
    O[(size_t)t * D_MODEL + h * HD + d] = __float2bfloat16(o);
}

// scale vectors may also be f32 either way (they are f32 in the reference);
// pass through directly.

// ---------------- host launcher ---------------------------------------------
extern "C" void kernel_launch(void* const* d_in, const int* in_sizes, int n_in,
                              void* d_out, int out_size) {
    // host-side diagnostics (appear in harness stdout/stderr)
    printf("DIAG n_in=%d out_size=%d sizes=", n_in, out_size);
    for (int i = 0; i < n_in; i++) printf("%d,", in_sizes[i]);
    printf("\n");
    fflush(stdout);

    // size-based binding (element counts; validated by cross-round consistency)
    const void *x = 0, *w_o = 0;
    const float *scale_q = 0, *scale_kv = 0;
    const void *p524[2] = {0, 0};
    const void *p262[3] = {0, 0, 0};
    const void *p65[2]  = {0, 0};
    int n524 = 0, n262 = 0, n65 = 0;

    for (int i = 0; i < n_in; i++) {
        switch (in_sizes[i]) {
            case 4194304: x = d_in[i]; break;
            case 1048576: w_o = d_in[i]; break;
            case 512:     scale_q  = (const float*)d_in[i]; break;
            case 256:     scale_kv = (const float*)d_in[i]; break;
            case 524288:  if (n524 < 2) p524[n524++] = d_in[i]; break;
            case 262144:  if (n262 < 3) p262[n262++] = d_in[i]; break;
            case 65536:   if (n65 < 2)  p65[n65++]  = d_in[i]; break;
            default: break;
        }
    }

    const void* w_dq  = p524[0];
    const void* w_uq  = p524[1];
    const void* sin_p = p262[0];
    const void* cos_p = p262[1];
    const void* w_dkv = p262[2];
    const void* w_uk  = p65[0];
    const void* w_uv  = p65[1];

    __nv_bfloat16 *xin, *sinb, *cosb, *wdq, *wuq, *wdkv, *wuk, *wuv, *wob;
    cudaGetSymbolAddress((void**)&xin,  g_xin);
    cudaGetSymbolAddress((void**)&sinb, g_sin);
    cudaGetSymbolAddress((void**)&cosb, g_cos);
    cudaGetSymbolAddress((void**)&wdq,  g_wdq);
    cudaGetSymbolAddress((void**)&wuq,  g_wuq);
    cudaGetSymbolAddress((void**)&wdkv, g_wdkv);
    cudaGetSymbolAddress((void**)&wuk,  g_wuk);
    cudaGetSymbolAddress((void**)&wuv,  g_wuv);
    cudaGetSymbolAddress((void**)&wob,  g_wo);

    __nv_bfloat16 *qlat_raw, *qlat, *qb, *q_ro, *kvraw, *kvlat, *kb, *k_ro, *vb, *attn;
    cudaGetSymbolAddress((void**)&qlat_raw, g_qlat_raw);
    cudaGetSymbolAddress((void**)&qlat,     g_qlat);
    cudaGetSymbolAddress((void**)&qb,       g_q);
    cudaGetSymbolAddress((void**)&q_ro,     g_q_ro);
    cudaGetSymbolAddress((void**)&kvraw,    g_kvraw);
    cudaGetSymbolAddress((void**)&kvlat,    g_kvlat);
    cudaGetSymbolAddress((void**)&kb,       g_k);
    cudaGetSymbolAddress((void**)&k_ro,     g_k_ro);
    cudaGetSymbolAddress((void**)&vb,       g_v);
    cudaGetSymbolAddress((void**)&attn,     g_attn);

    auto blocks = [](long long n) { return (int)((n + 255) / 256); };

    // 1) detect input storage dtype from x's bit patterns
    detect_kernel<<<1, 256>>>((const uint32_t*)x);

    // 2) normalize all bf16-semantic inputs into bf16 scratch
    convert_kernel<<<blocks(T_SEQ * D_MODEL), 256>>>(x,     xin,  T_SEQ * D_MODEL);
    convert_kernel<<<blocks(T_SEQ * HD),      256>>>(sin_p, sinb, T_SEQ * HD);
    convert_kernel<<<blocks(T_SEQ * HD),      256>>>(cos_p, cosb, T_SEQ * HD);
    convert_kernel<<<blocks(D_MODEL * QL),    256>>>(w_dq,  wdq,  D_MODEL * QL);
    convert_kernel<<<blocks(QL * D_MODEL),    256>>>(w_uq,  wuq,  QL * D_MODEL);
    convert_kernel<<<blocks(D_MODEL * KVL),   256>>>(w_dkv, wdkv, D_MODEL * KVL);
    convert_kernel<<<blocks(KVL * NKV * HD),  256>>>(w_uk,  wuk,  KVL * NKV * HD);
    convert_kernel<<<blocks(KVL * NKV * HD),  256>>>(w_uv,  wuv,  KVL * NKV * HD);
    convert_kernel<<<blocks(D_MODEL * D_MODEL), 256>>>(w_o, wob,  D_MODEL * D_MODEL);

    // 3) pipeline (identical math to round 3)
    gemm_naive<<<blocks((long long)T_SEQ * QL), 256>>>(xin, wdq, qlat_raw,
                                                       T_SEQ, QL, D_MODEL);
    rmsnorm_naive<<<T_SEQ, 256>>>(qlat_raw, scale_q, qlat, QL);

    gemm_naive<<<blocks((long long)T_SEQ * NH * HD), 256>>>(qlat, wuq, qb,
                                                            T_SEQ, NH * HD, QL);

    gemm_naive<<<blocks((long long)T_SEQ * KVL), 256>>>(xin, wdkv, kvraw,
                                                        T_SEQ, KVL, D_MODEL);
    rmsnorm_naive<<<T_SEQ, 256>>>(kvraw, scale_kv, kvlat, KVL);

    gemm_naive<<<blocks((long long)T_SEQ * NKV * HD), 256>>>(kvlat, wuk, kb,
                                                             T_SEQ, NKV * HD, KVL);
    gemm_naive<<<blocks((long long)T_SEQ * NKV * HD), 256>>>(kvlat, wuv, vb,
                                                             T_SEQ, NKV * HD, KVL);

    rope_naive<<<blocks((long long)T_SEQ * NH * HD), 256>>>(qb, sinb, cosb, q_ro, NH);
    rope_naive<<<blocks((long long)T_SEQ * NKV * HD), 256>>>(kb, sinb, cosb, k_ro, NKV);

    attn_naive<<<dim3(T_SEQ, NH), 64>>>(q_ro, k_ro, vb, attn);

    // 4) final projection, output dtype per detected flag
    gemm_out<<<blocks((long long)T_SEQ * D_MODEL), 256>>>(attn, wob, d_out,
                                                          T_SEQ, D_MODEL, D_MODEL);
}

// round 7
// speedup vs baseline: 4.1225x; 4.1225x over previous
#include <cuda_runtime.h>
#include <cuda_bf16.h>
#include <cstdint>

#define T_SEQ   4096
#define D_MODEL 1024
#define NH      16
#define NKV     4
#define HD      64
#define QL      512
#define KVL     256

// ---------------- scratch (device globals) -----------------------------------
static __device__ __nv_bfloat16 g_x_bf   [T_SEQ * D_MODEL];
static __device__ __nv_bfloat16 g_wdq_bf [D_MODEL * QL];
static __device__ __nv_bfloat16 g_wuq_bf [QL * D_MODEL];
static __device__ __nv_bfloat16 g_wdkv_bf[D_MODEL * KVL];
static __device__ __nv_bfloat16 g_wuk_bf [KVL * NKV * HD];
static __device__ __nv_bfloat16 g_wuv_bf [KVL * NKV * HD];
static __device__ __nv_bfloat16 g_wo_bf  [D_MODEL * D_MODEL];

static __device__ __nv_bfloat16 g_qlat_raw[T_SEQ * QL];       // bf16 (gemm out)
static __device__ __nv_bfloat16 g_qlat    [T_SEQ * QL];       // bf16 (rms out)
static __device__ __nv_bfloat16 g_q       [T_SEQ * NH * HD];
static __device__ __nv_bfloat16 g_q_ro    [T_SEQ * NH * HD];
static __device__ __nv_bfloat16 g_kvraw   [T_SEQ * KVL];
static __device__ __nv_bfloat16 g_kvlat   [T_SEQ * KVL];
static __device__ __nv_bfloat16 g_k       [T_SEQ * NKV * HD];
static __device__ __nv_bfloat16 g_k_ro    [T_SEQ * NKV * HD];
static __device__ __nv_bfloat16 g_v       [T_SEQ * NKV * HD];
static __device__ __nv_bfloat16 g_attn    [T_SEQ * D_MODEL];

// ---------------- helpers -----------------------------------------------------
__device__ __forceinline__ float bf16r(float x) {
    return __bfloat162float(__float2bfloat16(x));
}

// Deterministic ~1-ulp exp, fmaf-only (immune to -use_fast_math rewrites).
__device__ __forceinline__ float exp_acc(float x) {
    x = fmaxf(x, -87.0f);
    float n = rintf(x * 1.44269504088896340736f);
    float r = fmaf(n, -0.693145751953125f, x);       // ln2_hi
    r = fmaf(n, -1.42860677e-06f, r);                // ln2_lo
    float p = 1.9841269841e-04f;                     // 1/5040
    p = fmaf(p, r, 1.3888888889e-03f);               // 1/720
    p = fmaf(p, r, 8.3333333333e-03f);               // 1/120
    p = fmaf(p, r, 4.1666666667e-02f);               // 1/24
    p = fmaf(p, r, 1.6666666667e-01f);               // 1/6
    p = fmaf(p, r, 0.5f);
    p = fmaf(p, r, 1.0f);
    p = fmaf(p, r, 1.0f);
    int in = (int)n;
    return p * __int_as_float((in + 127) << 23);
}

// ---------------- convert: f32 storage of bf16 values -> packed bf16 ---------
__global__ void cvt_f32_to_bf16(const float* __restrict__ src,
                                __nv_bfloat16* __restrict__ dst, int n) {
    int i = blockIdx.x * blockDim.x + threadIdx.x;
    if (i < n) dst[i] = __float2bfloat16(src[i]);    // lossless
}

// ---------------- tiled GEMM: bf16 in, bf16 out (reference matmul semantics) -
__global__ void gemm_bf16(const __nv_bfloat16* __restrict__ A,
                          const __nv_bfloat16* __restrict__ B,
                          __nv_bfloat16* __restrict__ C,
                          int M, int N, int K) {
    __shared__ __nv_bfloat16 As[64][32];
    __shared__ __nv_bfloat16 Bs[32][64];

    const int tid = threadIdx.x;
    const int tx = tid & 15, ty = tid >> 4;
    const int row0 = blockIdx.y * 64, col0 = blockIdx.x * 64;
    const int a_r = tid >> 2, a_c = (tid & 3) * 8;
    const int b_r = tid >> 3, b_c = (tid & 7) * 8;

    float acc[4][4];
#pragma unroll
    for (int i = 0; i < 4; i++)
#pragma unroll
        for (int j = 0; j < 4; j++) acc[i][j] = 0.0f;

    for (int k0 = 0; k0 < K; k0 += 32) {
        *(uint4*)&As[a_r][a_c] = *(const uint4*)&A[(size_t)(row0 + a_r) * K + k0 + a_c];
        *(uint4*)&Bs[b_r][b_c] = *(const uint4*)&B[(size_t)(k0 + b_r) * N + col0 + b_c];
        __syncthreads();
#pragma unroll 8
        for (int kk = 0; kk < 32; kk++) {
            float a[4], b[4];
#pragma unroll
            for (int i = 0; i < 4; i++) a[i] = __bfloat162float(As[ty * 4 + i][kk]);
#pragma unroll
            for (int j = 0; j < 4; j++) b[j] = __bfloat162float(Bs[kk][tx * 4 + j]);
#pragma unroll
            for (int i = 0; i < 4; i++)
#pragma unroll
                for (int j = 0; j < 4; j++) acc[i][j] = fmaf(a[i], b[j], acc[i][j]);
        }
        __syncthreads();
    }
#pragma unroll
    for (int i = 0; i < 4; i++)
#pragma unroll
        for (int j = 0; j < 4; j++)
            C[(size_t)(row0 + ty * 4 + i) * N + col0 + tx * 4 + j] =
                __float2bfloat16(acc[i][j]);
}

// same, but writes bf16-rounded values into f32 output storage (final stage)
__global__ void gemm_bf16_outf32(const __nv_bfloat16* __restrict__ A,
                                 const __nv_bfloat16* __restrict__ B,
                                 float* __restrict__ C,
                                 int M, int N, int K) {
    __shared__ __nv_bfloat16 As[64][32];
    __shared__ __nv_bfloat16 Bs[32][64];

    const int tid = threadIdx.x;
    const int tx = tid & 15, ty = tid >> 4;
    const int row0 = blockIdx.y * 64, col0 = blockIdx.x * 64;
    const int a_r = tid >> 2, a_c = (tid & 3) * 8;
    const int b_r = tid >> 3, b_c = (tid & 7) * 8;

    float acc[4][4];
#pragma unroll
    for (int i = 0; i < 4; i++)
#pragma unroll
        for (int j = 0; j < 4; j++) acc[i][j] = 0.0f;

    for (int k0 = 0; k0 < K; k0 += 32) {
        *(uint4*)&As[a_r][a_c] = *(const uint4*)&A[(size_t)(row0 + a_r) * K + k0 + a_c];
        *(uint4*)&Bs[b_r][b_c] = *(const uint4*)&B[(size_t)(k0 + b_r) * N + col0 + b_c];
        __syncthreads();
#pragma unroll 8
        for (int kk = 0; kk < 32; kk++) {
            float a[4], b[4];
#pragma unroll
            for (int i = 0; i < 4; i++) a[i] = __bfloat162float(As[ty * 4 + i][kk]);
#pragma unroll
            for (int j = 0; j < 4; j++) b[j] = __bfloat162float(Bs[kk][tx * 4 + j]);
#pragma unroll
            for (int i = 0; i < 4; i++)
#pragma unroll
                for (int j = 0; j < 4; j++) acc[i][j] = fmaf(a[i], b[j], acc[i][j]);
        }
        __syncthreads();
    }
#pragma unroll
    for (int i = 0; i < 4; i++)
#pragma unroll
        for (int j = 0; j < 4; j++)
            C[(size_t)(row0 + ty * 4 + i) * N + col0 + tx * 4 + j] =
                bf16r(acc[i][j]);
}

// ---------------- RMSNorm: bf16 in -> f32 math (true div/sqrt) -> bf16 out ---
__global__ void rmsnorm_kernel(const __nv_bfloat16* __restrict__ in,
                               const float* __restrict__ scale,
                               __nv_bfloat16* __restrict__ out,
                               int cols) {
    const int row = blockIdx.x;
    const int tid = threadIdx.x;   // 256
    const __nv_bfloat16* x = in + (size_t)row * cols;
    __nv_bfloat16* y = out + (size_t)row * cols;

    __shared__ float red[256];
    float s = 0.0f;
    for (int c = tid; c < cols; c += 256) {
        float v = __bfloat162float(x[c]);
        s = fmaf(v, v, s);
    }
    red[tid] = s;
    __syncthreads();
    for (int off = 128; off > 0; off >>= 1) {
        if (tid < off) red[tid] += red[tid + off];
        __syncthreads();
    }
    float rms = __fsqrt_rn(red[0] / (float)cols + 1e-6f);
    for (int c = tid; c < cols; c += 256) {
        float v = __bfloat162float(x[c]);
        y[c] = __float2bfloat16(__fdiv_rn(v, rms) * scale[c]);
    }
}

// ---------------- RoPE: per-op bf16 rounding (reference bf16 arithmetic) -----
// sin/cos read from f32 storage (values are exactly bf16-valued).
__global__ void rope_kernel(const __nv_bfloat16* __restrict__ in,
                            const float* __restrict__ sin_t,
                            const float* __restrict__ cos_t,
                            __nv_bfloat16* __restrict__ out,
                            int heads) {
    int idx = blockIdx.x * blockDim.x + threadIdx.x;
    int total = T_SEQ * heads * HD;
    if (idx >= total) return;
    int d = idx & 63;
    int t = (idx >> 6) / heads;
    float xv = __bfloat162float(in[idx]);
    float rot = (d < 32) ? -__bfloat162float(in[idx + 32])
                         :  __bfloat162float(in[idx - 32]);
    float r1 = bf16r(xv * cos_t[t * HD + d]);
    float r2 = bf16r(rot * sin_t[t * HD + d]);
    out[idx] = __float2bfloat16(r1 + r2);
}

// ---------------- causal attention: 3-pass, reference-accurate softmax -------
// grid (T/64, NH), 128 threads: 2 threads per query row, 32 dims each.
// Pass 1: m = exact max of s (no exp). Pass 2: l = sum exp(s-m), accurate exp,
// no rescaling. Pass 3: p = bf16(exp(s-m) / l) (true division), PV f32 accum.
// Scores: s = bf16(q.k) * 0.125 (reference bf16 matmul then exact scale).
__global__ void __launch_bounds__(128, 4)
attn_kernel(const __nv_bfloat16* __restrict__ Q,
            const __nv_bfloat16* __restrict__ Kc,
            const __nv_bfloat16* __restrict__ Vc,
            __nv_bfloat16* __restrict__ O) {
    __shared__ float Ks[64][64];
    __shared__ float Vs[64][64];

    const int qtile = blockIdx.x;
    const int h = blockIdx.y;
    const int hk = h >> 2;             // GQA repeat = 4
    const int tid = threadIdx.x;
    const int r = tid >> 1;            // query row in tile
    const int hf = tid & 1;            // dim half
    const int t = qtile * 64 + r;
    const unsigned pair_mask = 0x3u << ((tid & 31) & ~1);

    float q[32];
    {
        const __nv_bfloat16* qp = Q + (size_t)t * D_MODEL + h * HD + hf * 32;
#pragma unroll
        for (int i = 0; i < 32; i++) q[i] = __bfloat162float(qp[i]);
    }

    const int ldj = tid >> 1;
    const int ldh = tid & 1;

    // tile loader: 32 bf16 -> f32 smem
    auto load_k = [&](int kt) {
        const __nv_bfloat16* kg = Kc + (size_t)(kt * 64 + ldj) * (NKV * HD) + hk * HD + ldh * 32;
#pragma unroll
        for (int u = 0; u < 4; u++) {
            uint4 w = ((const uint4*)kg)[u];
            const __nv_bfloat162* hh = (const __nv_bfloat162*)&w;
#pragma unroll
            for (int e = 0; e < 4; e++) {
                float2 f = __bfloat1622float2(hh[e]);
                Ks[ldj][ldh * 32 + u * 8 + e * 2]     = f.x;
                Ks[ldj][ldh * 32 + u * 8 + e * 2 + 1] = f.y;
            }
        }
    };
    auto load_v = [&](int kt) {
        const __nv_bfloat16* vg = Vc + (size_t)(kt * 64 + ldj) * (NKV * HD) + hk * HD + ldh * 32;
#pragma unroll
        for (int u = 0; u < 4; u++) {
            uint4 w = ((const uint4*)vg)[u];
            const __nv_bfloat162* hh = (const __nv_bfloat162*)&w;
#pragma unroll
            for (int e = 0; e < 4; e++) {
                float2 f = __bfloat1622float2(hh[e]);
                Vs[ldj][ldh * 32 + u * 8 + e * 2]     = f.x;
                Vs[ldj][ldh * 32 + u * 8 + e * 2 + 1] = f.y;
            }
        }
    };
    auto score = [&](int j) {
        float part = 0.0f;
        const float* kr = &Ks[j][hf * 32];
#pragma unroll
        for (int i = 0; i < 32; i++) part = fmaf(q[i], kr[i], part);
        return bf16r(part + __shfl_xor_sync(pair_mask, part, 1)) * 0.125f;
    };

    // ---- pass 1: exact max ----
    float m = -1e30f;
    for (int kt = 0; kt <= qtile; kt++) {
        __syncthreads();
        load_k(kt);
        __syncthreads();
        const int jmax = (kt == qtile) ? r : 63;
        for (int j = 0; j <= jmax; j++) m = fmaxf(m, score(j));
    }

    // ---- pass 2: l = sum exp(s - m), no rescaling ----
    float l = 0.0f;
    for (int kt = 0; kt <= qtile; kt++) {
        __syncthreads();
        load_k(kt);
        __syncthreads();
        const int jmax = (kt == qtile) ? r : 63;
        for (int j = 0; j <= jmax; j++) l += exp_acc(score(j) - m);
    }

    // ---- pass 3: probs (bf16-rounded true quotient) + PV ----
    float o[32];
#pragma unroll
    for (int i = 0; i < 32; i++) o[i] = 0.0f;

    for (int kt = 0; kt <= qtile; kt++) {
        __syncthreads();
        load_k(kt);
        load_v(kt);
        __syncthreads();
        const int jmax = (kt == qtile) ? r : 63;
        for (int j = 0; j <= jmax; j++) {
            float s = score(j);
            float p = bf16r(__fdiv_rn(exp_acc(s - m), l));
            const float* vr = &Vs[j][hf * 32];
#pragma unroll
            for (int i = 0; i < 32; i++) o[i] = fmaf(p, vr[i], o[i]);
        }
    }

    __nv_bfloat16* op = O + (size_t)t * D_MODEL + h * HD + hf * 32;
#pragma unroll
    for (int i = 0; i < 32; i++) op[i] = __float2bfloat16(o[i]);
}

// ---------------- host launcher ----------------------------------------------
extern "C" void kernel_launch(void* const* d_in, const int* in_sizes, int n_in,
                              void* d_out, int out_size) {
    (void)out_size;

    const float *x = 0, *w_o = 0, *scale_q = 0, *scale_kv = 0;
    const float *p524[2] = {0, 0}, *p262[3] = {0, 0, 0}, *p65[2] = {0, 0};
    int n524 = 0, n262 = 0, n65 = 0;
    for (int i = 0; i < n_in; i++) {
        switch (in_sizes[i]) {
            case 4194304: x = (const float*)d_in[i]; break;
            case 1048576: w_o = (const float*)d_in[i]; break;
            case 512:     scale_q  = (const float*)d_in[i]; break;
            case 256:     scale_kv = (const float*)d_in[i]; break;
            case 524288:  if (n524 < 2) p524[n524++] = (const float*)d_in[i]; break;
            case 262144:  if (n262 < 3) p262[n262++] = (const float*)d_in[i]; break;
            case 65536:   if (n65 < 2)  p65[n65++]  = (const float*)d_in[i]; break;
            default: break;
        }
    }
    const float* w_dq  = p524[0];
    const float* w_uq  = p524[1];
    const float* sin_p = p262[0];
    const float* cos_p = p262[1];
    const float* w_dkv = p262[2];
    const float* w_uk  = p65[0];
    const float* w_uv  = p65[1];
    float* out = (float*)d_out;

    __nv_bfloat16 *x_bf, *wdq_bf, *wuq_bf, *wdkv_bf, *wuk_bf, *wuv_bf, *wo_bf;
    __nv_bfloat16 *qlat_raw, *qlat, *qb, *q_ro, *kvraw, *kvlat, *kb, *k_ro, *vb, *attn;
    cudaGetSymbolAddress((void**)&x_bf,    g_x_bf);
    cudaGetSymbolAddress((void**)&wdq_bf,  g_wdq_bf);
    cudaGetSymbolAddress((void**)&wuq_bf,  g_wuq_bf);
    cudaGetSymbolAddress((void**)&wdkv_bf, g_wdkv_bf);
    cudaGetSymbolAddress((void**)&wuk_bf,  g_wuk_bf);
    cudaGetSymbolAddress((void**)&wuv_bf,  g_wuv_bf);
    cudaGetSymbolAddress((void**)&wo_bf,   g_wo_bf);
    cudaGetSymbolAddress((void**)&qlat_raw, g_qlat_raw);
    cudaGetSymbolAddress((void**)&qlat,     g_qlat);
    cudaGetSymbolAddress((void**)&qb,       g_q);
    cudaGetSymbolAddress((void**)&q_ro,     g_q_ro);
    cudaGetSymbolAddress((void**)&kvraw,    g_kvraw);
    cudaGetSymbolAddress((void**)&kvlat,    g_kvlat);
    cudaGetSymbolAddress((void**)&kb,       g_k);
    cudaGetSymbolAddress((void**)&k_ro,     g_k_ro);
    cudaGetSymbolAddress((void**)&vb,       g_v);
    cudaGetSymbolAddress((void**)&attn,     g_attn);

    auto blocks = [](long long n) { return (int)((n + 255) / 256); };

    // 1) lossless bf16 packing
    cvt_f32_to_bf16<<<blocks(T_SEQ * D_MODEL), 256>>>(x,     x_bf,    T_SEQ * D_MODEL);
    cvt_f32_to_bf16<<<blocks(D_MODEL * QL),    256>>>(w_dq,  wdq_bf,  D_MODEL * QL);
    cvt_f32_to_bf16<<<blocks(QL * D_MODEL),    256>>>(w_uq,  wuq_bf,  QL * D_MODEL);
    cvt_f32_to_bf16<<<blocks(D_MODEL * KVL),   256>>>(w_dkv, wdkv_bf, D_MODEL * KVL);
    cvt_f32_to_bf16<<<blocks(KVL * NKV * HD),  256>>>(w_uk,  wuk_bf,  KVL * NKV * HD);
    cvt_f32_to_bf16<<<blocks(KVL * NKV * HD),  256>>>(w_uv,  wuv_bf,  KVL * NKV * HD);
    cvt_f32_to_bf16<<<blocks(D_MODEL * D_MODEL), 256>>>(w_o, wo_bf,   D_MODEL * D_MODEL);

    // 2) q path (every matmul output bf16-rounded, like the reference)
    gemm_bf16<<<dim3(QL / 64, T_SEQ / 64), 256>>>(x_bf, wdq_bf, qlat_raw,
                                                  T_SEQ, QL, D_MODEL);
    rmsnorm_kernel<<<T_SEQ, 256>>>(qlat_raw, scale_q, qlat, QL);
    gemm_bf16<<<dim3((NH * HD) / 64, T_SEQ / 64), 256>>>(qlat, wuq_bf, qb,
                                                         T_SEQ, NH * HD, QL);

    // 3) kv path
    gemm_bf16<<<dim3(KVL / 64, T_SEQ / 64), 256>>>(x_bf, wdkv_bf, kvraw,
                                                   T_SEQ, KVL, D_MODEL);
    rmsnorm_kernel<<<T_SEQ, 256>>>(kvraw, scale_kv, kvlat, KVL);
    gemm_bf16<<<dim3((NKV * HD) / 64, T_SEQ / 64), 256>>>(kvlat, wuk_bf, kb,
                                                          T_SEQ, NKV * HD, KVL);
    gemm_bf16<<<dim3((NKV * HD) / 64, T_SEQ / 64), 256>>>(kvlat, wuv_bf, vb,
                                                          T_SEQ, NKV * HD, KVL);

    // 4) rope (bf16 per-op rounding)
    rope_kernel<<<blocks((long long)T_SEQ * NH * HD), 256>>>(qb, sin_p, cos_p, q_ro, NH);
    rope_kernel<<<blocks((long long)T_SEQ * NKV * HD), 256>>>(kb, sin_p, cos_p, k_ro, NKV);

    // 5) attention (bf16 scores, accurate 3-pass softmax, bf16 probs, bf16 out)
    attn_kernel<<<dim3(T_SEQ / 64, NH), 128>>>(q_ro, k_ro, vb, attn);

    // 6) final projection: bf16 matmul, bf16-rounded values in f32 storage
    gemm_bf16_outf32<<<dim3(D_MODEL / 64, T_SEQ / 64), 256>>>(attn, wo_bf, out,
                                                              T_SEQ, D_MODEL, D_MODEL);
}

// round 8
// speedup vs baseline: 5.9397x; 1.4408x over previous
#include <cuda_runtime.h>
#include <cuda_bf16.h>
#include <cstdint>

#define T_SEQ   4096
#define D_MODEL 1024
#define NH      16
#define NKV     4
#define HD      64
#define QL      512
#define KVL     256
#define NT      64                      // T_SEQ / 64 key tiles
#define TRI_ENT 8519680                 // 2080 tile-pairs * 4096 entries per head

// ---------------- scratch (device globals) -----------------------------------
static __device__ __nv_bfloat16 g_x_bf   [T_SEQ * D_MODEL];
static __device__ __nv_bfloat16 g_wdq_bf [D_MODEL * QL];
static __device__ __nv_bfloat16 g_wuq_bf [QL * D_MODEL];
static __device__ __nv_bfloat16 g_wdkv_bf[D_MODEL * KVL];
static __device__ __nv_bfloat16 g_wuk_bf [KVL * NKV * HD];
static __device__ __nv_bfloat16 g_wuv_bf [KVL * NKV * HD];
static __device__ __nv_bfloat16 g_wo_bf  [D_MODEL * D_MODEL];

static __device__ __nv_bfloat16 g_qlat_raw[T_SEQ * QL];
static __device__ __nv_bfloat16 g_qlat    [T_SEQ * QL];
static __device__ __nv_bfloat16 g_q       [T_SEQ * NH * HD];
static __device__ __nv_bfloat16 g_q_ro    [T_SEQ * NH * HD];
static __device__ __nv_bfloat16 g_kvraw   [T_SEQ * KVL];
static __device__ __nv_bfloat16 g_kvlat   [T_SEQ * KVL];
static __device__ __nv_bfloat16 g_k       [T_SEQ * NKV * HD];
static __device__ __nv_bfloat16 g_k_ro    [T_SEQ * NKV * HD];
static __device__ __nv_bfloat16 g_v       [T_SEQ * NKV * HD];
static __device__ __nv_bfloat16 g_attn    [T_SEQ * D_MODEL];

// causal-packed raw scores: per head, per qtile, [key j][row r], bf16(q.k)
static __device__ __nv_bfloat16 g_scores[(size_t)NH * TRI_ENT];

// ---------------- helpers -----------------------------------------------------
__device__ __forceinline__ float bf16r(float x) {
    return __bfloat162float(__float2bfloat16(x));
}

// Deterministic ~1-ulp exp, fmaf-only (identical to round 7).
__device__ __forceinline__ float exp_acc(float x) {
    x = fmaxf(x, -87.0f);
    float n = rintf(x * 1.44269504088896340736f);
    float r = fmaf(n, -0.693145751953125f, x);
    r = fmaf(n, -1.42860677e-06f, r);
    float p = 1.9841269841e-04f;
    p = fmaf(p, r, 1.3888888889e-03f);
    p = fmaf(p, r, 8.3333333333e-03f);
    p = fmaf(p, r, 4.1666666667e-02f);
    p = fmaf(p, r, 1.6666666667e-01f);
    p = fmaf(p, r, 0.5f);
    p = fmaf(p, r, 1.0f);
    p = fmaf(p, r, 1.0f);
    int in = (int)n;
    return p * __int_as_float((in + 127) << 23);
}

// ---------------- convert: f32 storage of bf16 values -> packed bf16 ---------
__global__ void cvt_f32_to_bf16(const float* __restrict__ src,
                                __nv_bfloat16* __restrict__ dst, int n) {
    int i = blockIdx.x * blockDim.x + threadIdx.x;
    if (i < n) dst[i] = __float2bfloat16(src[i]);
}

// ---------------- big-tile GEMM: 128x64 block, 8x4 micro, f32 smem -----------
// Accumulation: k strictly ascending per output accumulator -> bit-identical
// to the round-7 GEMM. outf32=0: bf16 out. outf32=1: bf16-rounded into f32.
__global__ void __launch_bounds__(256, 2)
gemm_big(const __nv_bfloat16* __restrict__ A,
         const __nv_bfloat16* __restrict__ B,
         void* __restrict__ C,
         int M, int N, int K, int outf32) {
    __shared__ float As[128][36];   // [row][k], row stride 144B (16B-aligned)
    __shared__ float Bs[32][68];    // [k][col], row stride 272B (16B-aligned)

    const int tid = threadIdx.x;
    const int tx = tid & 15;        // 0..15 -> 4 cols each
    const int ty = tid >> 4;        // 0..15 -> 8 rows each
    const int row0 = blockIdx.y * 128;
    const int col0 = blockIdx.x * 64;

    const int a_row  = tid >> 1;        // 0..127
    const int a_half = tid & 1;         // k half: 0 -> [0,16), 1 -> [16,32)
    const int b_row  = tid >> 3;        // 0..31
    const int b_col  = (tid & 7) * 8;   // 0..56

    float acc[8][4];
#pragma unroll
    for (int i = 0; i < 8; i++)
#pragma unroll
        for (int j = 0; j < 4; j++) acc[i][j] = 0.0f;

    for (int k0 = 0; k0 < K; k0 += 32) {
        // load A tile (bf16 -> f32, exact)
        {
            const __nv_bfloat16* ap = A + (size_t)(row0 + a_row) * K + k0 + a_half * 16;
            uint4 w0 = ((const uint4*)ap)[0];
            uint4 w1 = ((const uint4*)ap)[1];
            float vals[16];
            const __nv_bfloat162* h0 = (const __nv_bfloat162*)&w0;
            const __nv_bfloat162* h1 = (const __nv_bfloat162*)&w1;
#pragma unroll
            for (int e = 0; e < 4; e++) {
                float2 f = __bfloat1622float2(h0[e]);
                vals[e * 2] = f.x; vals[e * 2 + 1] = f.y;
                float2 g = __bfloat1622float2(h1[e]);
                vals[8 + e * 2] = g.x; vals[8 + e * 2 + 1] = g.y;
            }
            float* dst = &As[a_row][a_half * 16];
#pragma unroll
            for (int u = 0; u < 4; u++)
                *(float4*)&dst[u * 4] = make_float4(vals[u * 4], vals[u * 4 + 1],
                                                    vals[u * 4 + 2], vals[u * 4 + 3]);
        }
        // load B tile (bf16 -> f32, exact)
        {
            const __nv_bfloat16* bp = B + (size_t)(k0 + b_row) * N + col0 + b_col;
            uint4 w = *(const uint4*)bp;
            const __nv_bfloat162* hh = (const __nv_bfloat162*)&w;
            float vals[8];
#pragma unroll
            for (int e = 0; e < 4; e++) {
                float2 f = __bfloat1622float2(hh[e]);
                vals[e * 2] = f.x; vals[e * 2 + 1] = f.y;
            }
            *(float4*)&Bs[b_row][b_col]     = make_float4(vals[0], vals[1], vals[2], vals[3]);
            *(float4*)&Bs[b_row][b_col + 4] = make_float4(vals[4], vals[5], vals[6], vals[7]);
        }
        __syncthreads();

#pragma unroll 4
        for (int kk = 0; kk < 32; kk++) {
            float b0 = Bs[kk][tx * 4], b1 = Bs[kk][tx * 4 + 1],
                  b2 = Bs[kk][tx * 4 + 2], b3 = Bs[kk][tx * 4 + 3];
#pragma unroll
            for (int i = 0; i < 8; i++) {
                float a = As[ty * 8 + i][kk];
                acc[i][0] = fmaf(a, b0, acc[i][0]);
                acc[i][1] = fmaf(a, b1, acc[i][1]);
                acc[i][2] = fmaf(a, b2, acc[i][2]);
                acc[i][3] = fmaf(a, b3, acc[i][3]);
            }
        }
        __syncthreads();
    }

    if (outf32) {
        float* Cf = (float*)C;
#pragma unroll
        for (int i = 0; i < 8; i++) {
            float4 v = make_float4(bf16r(acc[i][0]), bf16r(acc[i][1]),
                                   bf16r(acc[i][2]), bf16r(acc[i][3]));
            *(float4*)&Cf[(size_t)(row0 + ty * 8 + i) * N + col0 + tx * 4] = v;
        }
    } else {
        __nv_bfloat16* Cb = (__nv_bfloat16*)C;
#pragma unroll
        for (int i = 0; i < 8; i++) {
            __nv_bfloat162 lo = __floats2bfloat162_rn(acc[i][0], acc[i][1]);
            __nv_bfloat162 hi = __floats2bfloat162_rn(acc[i][2], acc[i][3]);
            uint2 w = make_uint2(*(uint32_t*)&lo, *(uint32_t*)&hi);
            *(uint2*)&Cb[(size_t)(row0 + ty * 8 + i) * N + col0 + tx * 4] = w;
        }
    }
}

// ---------------- RMSNorm (identical to round 7) -----------------------------
__global__ void rmsnorm_kernel(const __nv_bfloat16* __restrict__ in,
                               const float* __restrict__ scale,
                               __nv_bfloat16* __restrict__ out,
                               int cols) {
    const int row = blockIdx.x;
    const int tid = threadIdx.x;
    const __nv_bfloat16* x = in + (size_t)row * cols;
    __nv_bfloat16* y = out + (size_t)row * cols;

    __shared__ float red[256];
    float s = 0.0f;
    for (int c = tid; c < cols; c += 256) {
        float v = __bfloat162float(x[c]);
        s = fmaf(v, v, s);
    }
    red[tid] = s;
    __syncthreads();
    for (int off = 128; off > 0; off >>= 1) {
        if (tid < off) red[tid] += red[tid + off];
        __syncthreads();
    }
    float rms = __fsqrt_rn(red[0] / (float)cols + 1e-6f);
    for (int c = tid; c < cols; c += 256) {
        float v = __bfloat162float(x[c]);
        y[c] = __float2bfloat16(__fdiv_rn(v, rms) * scale[c]);
    }
}

// ---------------- RoPE (identical to round 7) --------------------------------
__global__ void rope_kernel(const __nv_bfloat16* __restrict__ in,
                            const float* __restrict__ sin_t,
                            const float* __restrict__ cos_t,
                            __nv_bfloat16* __restrict__ out,
                            int heads) {
    int idx = blockIdx.x * blockDim.x + threadIdx.x;
    int total = T_SEQ * heads * HD;
    if (idx >= total) return;
    int d = idx & 63;
    int t = (idx >> 6) / heads;
    float xv = __bfloat162float(in[idx]);
    float rot = (d < 32) ? -__bfloat162float(in[idx + 32])
                         :  __bfloat162float(in[idx - 32]);
    float r1 = bf16r(xv * cos_t[t * HD + d]);
    float r2 = bf16r(rot * sin_t[t * HD + d]);
    out[idx] = __float2bfloat16(r1 + r2);
}

// ---------------- causal attention: QK once, scores via gmem scratch ---------
// Same arithmetic in the same order as round 7's 3-pass kernel; the only
// change is that passes 2/3 read the stored bf16(q.k) instead of recomputing.
__global__ void __launch_bounds__(128, 4)
attn_kernel(const __nv_bfloat16* __restrict__ Q,
            const __nv_bfloat16* __restrict__ Kc,
            const __nv_bfloat16* __restrict__ Vc,
            __nv_bfloat16* __restrict__ O,
            __nv_bfloat16* __restrict__ Sc) {
    __shared__ float Ks[64][64];
    __shared__ float Vs[64][64];

    const int qtile = blockIdx.x;
    const int h = blockIdx.y;
    const int hk = h >> 2;
    const int tid = threadIdx.x;
    const int r = tid >> 1;
    const int hf = tid & 1;
    const int t = qtile * 64 + r;
    const unsigned pair_mask = 0x3u << ((tid & 31) & ~1);

    // score scratch base for this (h, qtile)
    const size_t sbase = (size_t)h * TRI_ENT +
                         (size_t)qtile * (qtile + 1) / 2 * 4096;

    float q[32];
    {
        const __nv_bfloat16* qp = Q + (size_t)t * D_MODEL + h * HD + hf * 32;
#pragma unroll
        for (int i = 0; i < 32; i++) q[i] = __bfloat162float(qp[i]);
    }

    const int ldj = tid >> 1;
    const int ldh = tid & 1;

    auto load_k = [&](int kt) {
        const __nv_bfloat16* kg = Kc + (size_t)(kt * 64 + ldj) * (NKV * HD) + hk * HD + ldh * 32;
#pragma unroll
        for (int u = 0; u < 4; u++) {
            uint4 w = ((const uint4*)kg)[u];
            const __nv_bfloat162* hh = (const __nv_bfloat162*)&w;
#pragma unroll
            for (int e = 0; e < 4; e++) {
                float2 f = __bfloat1622float2(hh[e]);
                Ks[ldj][ldh * 32 + u * 8 + e * 2]     = f.x;
                Ks[ldj][ldh * 32 + u * 8 + e * 2 + 1] = f.y;
            }
        }
    };
    auto load_v = [&](int kt) {
        const __nv_bfloat16* vg = Vc + (size_t)(kt * 64 + ldj) * (NKV * HD) + hk * HD + ldh * 32;
#pragma unroll
        for (int u = 0; u < 4; u++) {
            uint4 w = ((const uint4*)vg)[u];
            const __nv_bfloat162* hh = (const __nv_bfloat162*)&w;
#pragma unroll
            for (int e = 0; e < 4; e++) {
                float2 f = __bfloat1622float2(hh[e]);
                Vs[ldj][ldh * 32 + u * 8 + e * 2]     = f.x;
                Vs[ldj][ldh * 32 + u * 8 + e * 2 + 1] = f.y;
            }
        }
    };

    // ---- pass 1: compute scores once, store bf16(q.k), track exact max ----
    float m = -1e30f;
    for (int kt = 0; kt <= qtile; kt++) {
        __syncthreads();
        load_k(kt);
        __syncthreads();
        const int jmax = (kt == qtile) ? r : 63;
        for (int j = 0; j <= jmax; j++) {
            float part = 0.0f;
            const float* kr = &Ks[j][hf * 32];
#pragma unroll
            for (int i = 0; i < 32; i++) part = fmaf(q[i], kr[i], part);
            float sum = part + __shfl_xor_sync(pair_mask, part, 1);
            __nv_bfloat16 sb = __float2bfloat16(sum);
            if (hf == 0) Sc[sbase + (size_t)(kt * 64 + j) * 64 + r] = sb;
            float s = __bfloat162float(sb) * 0.125f;
            m = fmaxf(m, s);
        }
    }
    __syncthreads();   // score writes visible block-wide

    // ---- pass 2: l = sum exp(s - m) from stored scores ----
    float l = 0.0f;
    for (int kt = 0; kt <= qtile; kt++) {
        const int jmax = (kt == qtile) ? r : 63;
        for (int j = 0; j <= jmax; j++) {
            float s = __bfloat162float(Sc[sbase + (size_t)(kt * 64 + j) * 64 + r]) * 0.125f;
            l += exp_acc(s - m);
        }
    }

    // ---- pass 3: probs (bf16-rounded true quotient) + PV ----
    float o[32];
#pragma unroll
    for (int i = 0; i < 32; i++) o[i] = 0.0f;

    for (int kt = 0; kt <= qtile; kt++) {
        __syncthreads();
        load_v(kt);
        __syncthreads();
        const int jmax = (kt == qtile) ? r : 63;
        for (int j = 0; j <= jmax; j++) {
            float s = __bfloat162float(Sc[sbase + (size_t)(kt * 64 + j) * 64 + r]) * 0.125f;
            float p = bf16r(__fdiv_rn(exp_acc(s - m), l));
            const float* vr = &Vs[j][hf * 32];
#pragma unroll
            for (int i = 0; i < 32; i++) o[i] = fmaf(p, vr[i], o[i]);
        }
    }

    __nv_bfloat16* op = O + (size_t)t * D_MODEL + h * HD + hf * 32;
#pragma unroll
    for (int i = 0; i < 32; i++) op[i] = __float2bfloat16(o[i]);
}

// ---------------- host launcher ----------------------------------------------
extern "C" void kernel_launch(void* const* d_in, const int* in_sizes, int n_in,
                              void* d_out, int out_size) {
    (void)out_size;

    const float *x = 0, *w_o = 0, *scale_q = 0, *scale_kv = 0;
    const float *p524[2] = {0, 0}, *p262[3] = {0, 0, 0}, *p65[2] = {0, 0};
    int n524 = 0, n262 = 0, n65 = 0;
    for (int i = 0; i < n_in; i++) {
        switch (in_sizes[i]) {
            case 4194304: x = (const float*)d_in[i]; break;
            case 1048576: w_o = (const float*)d_in[i]; break;
            case 512:     scale_q  = (const float*)d_in[i]; break;
            case 256:     scale_kv = (const float*)d_in[i]; break;
            case 524288:  if (n524 < 2) p524[n524++] = (const float*)d_in[i]; break;
            case 262144:  if (n262 < 3) p262[n262++] = (const float*)d_in[i]; break;
            case 65536:   if (n65 < 2)  p65[n65++]  = (const float*)d_in[i]; break;
            default: break;
        }
    }
    const float* w_dq  = p524[0];
    const float* w_uq  = p524[1];
    const float* sin_p = p262[0];
    const float* cos_p = p262[1];
    const float* w_dkv = p262[2];
    const float* w_uk  = p65[0];
    const float* w_uv  = p65[1];
    float* out = (float*)d_out;

    __nv_bfloat16 *x_bf, *wdq_bf, *wuq_bf, *wdkv_bf, *wuk_bf, *wuv_bf, *wo_bf;
    __nv_bfloat16 *qlat_raw, *qlat, *qb, *q_ro, *kvraw, *kvlat, *kb, *k_ro, *vb, *attn, *scores;
    cudaGetSymbolAddress((void**)&x_bf,    g_x_bf);
    cudaGetSymbolAddress((void**)&wdq_bf,  g_wdq_bf);
    cudaGetSymbolAddress((void**)&wuq_bf,  g_wuq_bf);
    cudaGetSymbolAddress((void**)&wdkv_bf, g_wdkv_bf);
    cudaGetSymbolAddress((void**)&wuk_bf,  g_wuk_bf);
    cudaGetSymbolAddress((void**)&wuv_bf,  g_wuv_bf);
    cudaGetSymbolAddress((void**)&wo_bf,   g_wo_bf);
    cudaGetSymbolAddress((void**)&qlat_raw, g_qlat_raw);
    cudaGetSymbolAddress((void**)&qlat,     g_qlat);
    cudaGetSymbolAddress((void**)&qb,       g_q);
    cudaGetSymbolAddress((void**)&q_ro,     g_q_ro);
    cudaGetSymbolAddress((void**)&kvraw,    g_kvraw);
    cudaGetSymbolAddress((void**)&kvlat,    g_kvlat);
    cudaGetSymbolAddress((void**)&kb,       g_k);
    cudaGetSymbolAddress((void**)&k_ro,     g_k_ro);
    cudaGetSymbolAddress((void**)&vb,       g_v);
    cudaGetSymbolAddress((void**)&attn,     g_attn);
    cudaGetSymbolAddress((void**)&scores,   g_scores);

    auto blocks = [](long long n) { return (int)((n + 255) / 256); };

    // 1) lossless bf16 packing
    cvt_f32_to_bf16<<<blocks(T_SEQ * D_MODEL), 256>>>(x,     x_bf,    T_SEQ * D_MODEL);
    cvt_f32_to_bf16<<<blocks(D_MODEL * QL),    256>>>(w_dq,  wdq_bf,  D_MODEL * QL);
    cvt_f32_to_bf16<<<blocks(QL * D_MODEL),    256>>>(w_uq,  wuq_bf,  QL * D_MODEL);
    cvt_f32_to_bf16<<<blocks(D_MODEL * KVL),   256>>>(w_dkv, wdkv_bf, D_MODEL * KVL);
    cvt_f32_to_bf16<<<blocks(KVL * NKV * HD),  256>>>(w_uk,  wuk_bf,  KVL * NKV * HD);
    cvt_f32_to_bf16<<<blocks(KVL * NKV * HD),  256>>>(w_uv,  wuv_bf,  KVL * NKV * HD);
    cvt_f32_to_bf16<<<blocks(D_MODEL * D_MODEL), 256>>>(w_o, wo_bf,   D_MODEL * D_MODEL);

    // 2) q path
    gemm_big<<<dim3(QL / 64, T_SEQ / 128), 256>>>(x_bf, wdq_bf, qlat_raw,
                                                  T_SEQ, QL, D_MODEL, 0);
    rmsnorm_kernel<<<T_SEQ, 256>>>(qlat_raw, scale_q, qlat, QL);
    gemm_big<<<dim3((NH * HD) / 64, T_SEQ / 128), 256>>>(qlat, wuq_bf, qb,
                                                         T_SEQ, NH * HD, QL, 0);

    // 3) kv path
    gemm_big<<<dim3(KVL / 64, T_SEQ / 128), 256>>>(x_bf, wdkv_bf, kvraw,
                                                   T_SEQ, KVL, D_MODEL, 0);
    rmsnorm_kernel<<<T_SEQ, 256>>>(kvraw, scale_kv, kvlat, KVL);
    gemm_big<<<dim3((NKV * HD) / 64, T_SEQ / 128), 256>>>(kvlat, wuk_bf, kb,
                                                          T_SEQ, NKV * HD, KVL, 0);
    gemm_big<<<dim3((NKV * HD) / 64, T_SEQ / 128), 256>>>(kvlat, wuv_bf, vb,
                                                          T_SEQ, NKV * HD, KVL, 0);

    // 4) rope
    rope_kernel<<<blocks((long long)T_SEQ * NH * HD), 256>>>(qb, sin_p, cos_p, q_ro, NH);
    rope_kernel<<<blocks((long long)T_SEQ * NKV * HD), 256>>>(kb, sin_p, cos_p, k_ro, NKV);

    // 5) attention (QK once; scores via scratch; same FP order as round 7)
    attn_kernel<<<dim3(T_SEQ / 64, NH), 128>>>(q_ro, k_ro, vb, attn, scores);

    // 6) final projection
    gemm_big<<<dim3(D_MODEL / 64, T_SEQ / 128), 256>>>(attn, wo_bf, out,
                                                       T_SEQ, D_MODEL, D_MODEL, 1);
}

// round 9
// speedup vs baseline: 6.1250x; 1.0312x over previous
#include <cuda_runtime.h>
#include <cuda_bf16.h>
#include <cstdint>

#define T_SEQ   4096
#define D_MODEL 1024
#define NH      16
#define NKV     4
#define HD      64
#define QL      512
#define KVL     256
#define NT      64
#define TRI_ENT 8519680                 // 2080 tile-pairs * 4096 entries per head

// ---------------- scratch (device globals; all f32, values bf16-rounded) -----
static __device__ float g_qlat_raw[T_SEQ * QL];
static __device__ float g_qlat    [T_SEQ * QL];
static __device__ float g_q       [T_SEQ * NH * HD];
static __device__ float g_q_ro    [T_SEQ * NH * HD];
static __device__ float g_kvraw   [T_SEQ * KVL];
static __device__ float g_kvlat   [T_SEQ * KVL];
static __device__ float g_k       [T_SEQ * NKV * HD];
static __device__ float g_k_ro    [T_SEQ * NKV * HD];
static __device__ float g_v       [T_SEQ * NKV * HD];
static __device__ float g_attn    [T_SEQ * D_MODEL];

// causal-packed raw scores: per head, per qtile, [key j][row r], bf16(q.k)
static __device__ __nv_bfloat16 g_scores[(size_t)NH * TRI_ENT];

// ---------------- helpers -----------------------------------------------------
__device__ __forceinline__ float bf16r(float x) {
    return __bfloat162float(__float2bfloat16(x));
}

typedef unsigned long long u64;

__device__ __forceinline__ u64 pack2(float lo, float hi) {
    u64 r;
    asm("mov.b64 %0, {%1, %2};" : "=l"(r) : "f"(lo), "f"(hi));
    return r;
}
__device__ __forceinline__ void unpack2(u64 v, float& lo, float& hi) {
    asm("mov.b64 {%0, %1}, %2;" : "=f"(lo), "=f"(hi) : "l"(v));
}
// packed IEEE f32 FMA (FFMA2) — per-element identical to scalar fmaf
__device__ __forceinline__ u64 fma2(u64 a, u64 b, u64 c) {
    u64 d;
    asm("fma.rn.f32x2 %0, %1, %2, %3;" : "=l"(d) : "l"(a), "l"(b), "l"(c));
    return d;
}

// Deterministic ~1-ulp exp, fmaf-only (identical to rounds 7/8).
__device__ __forceinline__ float exp_acc(float x) {
    x = fmaxf(x, -87.0f);
    float n = rintf(x * 1.44269504088896340736f);
    float r = fmaf(n, -0.693145751953125f, x);
    r = fmaf(n, -1.42860677e-06f, r);
    float p = 1.9841269841e-04f;
    p = fmaf(p, r, 1.3888888889e-03f);
    p = fmaf(p, r, 8.3333333333e-03f);
    p = fmaf(p, r, 4.1666666667e-02f);
    p = fmaf(p, r, 1.6666666667e-01f);
    p = fmaf(p, r, 0.5f);
    p = fmaf(p, r, 1.0f);
    p = fmaf(p, r, 1.0f);
    int in = (int)n;
    return p * __int_as_float((in + 127) << 23);
}

// ---------------- GEMM: f32 in (bf16-valued), bf16r f32 out, FFMA2 core ------
// 128x64 block, 8x4 micro (as 8x2 f32x2), BK=32, 256 threads.
// Each accumulator element's k-chain is strictly ascending -> bit-identical
// to the round-8 scalar GEMM.
__global__ void __launch_bounds__(256, 2)
gemm_ffma2(const float* __restrict__ A,
           const float* __restrict__ B,
           float* __restrict__ C,
           int M, int N, int K) {
    __shared__ float As[128][36];
    __shared__ float Bs[32][68];

    const int tid = threadIdx.x;
    const int tx = tid & 15;
    const int ty = tid >> 4;
    const int row0 = blockIdx.y * 128;
    const int col0 = blockIdx.x * 64;

    const int a_row  = tid >> 1;
    const int a_half = tid & 1;
    const int b_row  = tid >> 3;
    const int b_col  = (tid & 7) * 8;

    u64 acc2[8][2];
#pragma unroll
    for (int i = 0; i < 8; i++) { acc2[i][0] = 0ull; acc2[i][1] = 0ull; }

    for (int k0 = 0; k0 < K; k0 += 32) {
        {
            const float* ap = A + (size_t)(row0 + a_row) * K + k0 + a_half * 16;
            float* dst = &As[a_row][a_half * 16];
#pragma unroll
            for (int u = 0; u < 4; u++)
                *(float4*)&dst[u * 4] = ((const float4*)ap)[u];
        }
        {
            const float* bp = B + (size_t)(k0 + b_row) * N + col0 + b_col;
            *(float4*)&Bs[b_row][b_col]     = ((const float4*)bp)[0];
            *(float4*)&Bs[b_row][b_col + 4] = ((const float4*)bp)[1];
        }
        __syncthreads();

#pragma unroll 4
        for (int kk = 0; kk < 32; kk++) {
            u64 b01 = *(const u64*)&Bs[kk][tx * 4];
            u64 b23 = *(const u64*)&Bs[kk][tx * 4 + 2];
#pragma unroll
            for (int i = 0; i < 8; i++) {
                float a = As[ty * 8 + i][kk];
                u64 aa = pack2(a, a);
                acc2[i][0] = fma2(aa, b01, acc2[i][0]);
                acc2[i][1] = fma2(aa, b23, acc2[i][1]);
            }
        }
        __syncthreads();
    }

#pragma unroll
    for (int i = 0; i < 8; i++) {
        float c0, c1, c2, c3;
        unpack2(acc2[i][0], c0, c1);
        unpack2(acc2[i][1], c2, c3);
        float4 v = make_float4(bf16r(c0), bf16r(c1), bf16r(c2), bf16r(c3));
        *(float4*)&C[(size_t)(row0 + ty * 8 + i) * N + col0 + tx * 4] = v;
    }
}

// ---------------- RMSNorm: f32 in -> bf16r f32 out (same FP ops) -------------
__global__ void rmsnorm_kernel(const float* __restrict__ in,
                               const float* __restrict__ scale,
                               float* __restrict__ out,
                               int cols) {
    const int row = blockIdx.x;
    const int tid = threadIdx.x;
    const float* x = in + (size_t)row * cols;
    float* y = out + (size_t)row * cols;

    __shared__ float red[256];
    float s = 0.0f;
    for (int c = tid; c < cols; c += 256) {
        float v = x[c];
        s = fmaf(v, v, s);
    }
    red[tid] = s;
    __syncthreads();
    for (int off = 128; off > 0; off >>= 1) {
        if (tid < off) red[tid] += red[tid + off];
        __syncthreads();
    }
    float rms = __fsqrt_rn(red[0] / (float)cols + 1e-6f);
    for (int c = tid; c < cols; c += 256)
        y[c] = bf16r(__fdiv_rn(x[c], rms) * scale[c]);
}

// ---------------- RoPE: f32 in/out, per-op bf16 rounding (same FP ops) -------
__global__ void rope_kernel(const float* __restrict__ in,
                            const float* __restrict__ sin_t,
                            const float* __restrict__ cos_t,
                            float* __restrict__ out,
                            int heads) {
    int idx = blockIdx.x * blockDim.x + threadIdx.x;
    int total = T_SEQ * heads * HD;
    if (idx >= total) return;
    int d = idx & 63;
    int t = (idx >> 6) / heads;
    float xv = in[idx];
    float rot = (d < 32) ? -in[idx + 32] : in[idx - 32];
    float r1 = bf16r(xv * cos_t[t * HD + d]);
    float r2 = bf16r(rot * sin_t[t * HD + d]);
    out[idx] = bf16r(r1 + r2);
}

// ---------------- causal attention ------------------------------------------
// Same FP values and accumulation order as round 8. New: LPT block order,
// pairwise exp/div dedup across the lane pair, FFMA2 PV.
__global__ void __launch_bounds__(128, 4)
attn_kernel(const float* __restrict__ Q,
            const float* __restrict__ Kc,
            const float* __restrict__ Vc,
            float* __restrict__ O,
            __nv_bfloat16* __restrict__ Sc) {
    __shared__ float Ks[64][64];
    __shared__ float Vs[64][64];

    const int qtile = (int)gridDim.x - 1 - (int)blockIdx.x;   // heavy blocks first
    const int h = blockIdx.y;
    const int hk = h >> 2;
    const int tid = threadIdx.x;
    const int r = tid >> 1;
    const int hf = tid & 1;
    const int t = qtile * 64 + r;
    const unsigned pair_mask = 0x3u << ((tid & 31) & ~1);

    const size_t sbase = (size_t)h * TRI_ENT +
                         (size_t)qtile * (qtile + 1) / 2 * 4096;

    float q[32];
    {
        const float* qp = Q + (size_t)t * D_MODEL + h * HD + hf * 32;
#pragma unroll
        for (int u = 0; u < 8; u++)
            *(float4*)&q[u * 4] = ((const float4*)qp)[u];
    }

    const int ldj = tid >> 1;
    const int ldh = tid & 1;

    auto load_k = [&](int kt) {
        const float* kg = Kc + (size_t)(kt * 64 + ldj) * (NKV * HD) + hk * HD + ldh * 32;
        float4* dst = (float4*)&Ks[ldj][ldh * 32];
#pragma unroll
        for (int u = 0; u < 8; u++) dst[u] = ((const float4*)kg)[u];
    };
    auto load_v = [&](int kt) {
        const float* vg = Vc + (size_t)(kt * 64 + ldj) * (NKV * HD) + hk * HD + ldh * 32;
        float4* dst = (float4*)&Vs[ldj][ldh * 32];
#pragma unroll
        for (int u = 0; u < 8; u++) dst[u] = ((const float4*)vg)[u];
    };

    // ---- pass 1: QK once, store bf16(q.k), track exact max ----
    float m = -1e30f;
    for (int kt = 0; kt <= qtile; kt++) {
        __syncthreads();
        load_k(kt);
        __syncthreads();
        const int jmax = (kt == qtile) ? r : 63;
        for (int j = 0; j <= jmax; j++) {
            float part = 0.0f;
            const float* kr = &Ks[j][hf * 32];
#pragma unroll
            for (int i = 0; i < 32; i++) part = fmaf(q[i], kr[i], part);
            float sum = part + __shfl_xor_sync(pair_mask, part, 1);
            __nv_bfloat16 sb = __float2bfloat16(sum);
            if (hf == 0) Sc[sbase + (size_t)(kt * 64 + j) * 64 + r] = sb;
            float s = __bfloat162float(sb) * 0.125f;
            m = fmaxf(m, s);
        }
    }
    __syncthreads();

    // ---- pass 2: l = sum exp(s - m), pairwise exp dedup, ascending order ----
    float l = 0.0f;
    for (int kt = 0; kt <= qtile; kt++) {
        const int jmax = (kt == qtile) ? r : 63;
        int j = 0;
        for (; j + 1 <= jmax; j += 2) {
            int jm = j + hf;   // lane0 -> even, lane1 -> odd
            float s = __bfloat162float(Sc[sbase + (size_t)(kt * 64 + jm) * 64 + r]) * 0.125f;
            float e = exp_acc(s - m);
            float eo = __shfl_xor_sync(pair_mask, e, 1);
            float e_even = hf ? eo : e;
            float e_odd  = hf ? e  : eo;
            l += e_even;
            l += e_odd;
        }
        if (j <= jmax) {
            float s = __bfloat162float(Sc[sbase + (size_t)(kt * 64 + j) * 64 + r]) * 0.125f;
            l += exp_acc(s - m);
        }
    }

    // ---- pass 3: probs pairwise, PV with FFMA2 (per-element chains intact) --
    u64 o2[16];
#pragma unroll
    for (int i = 0; i < 16; i++) o2[i] = 0ull;

    for (int kt = 0; kt <= qtile; kt++) {
        __syncthreads();
        load_v(kt);
        __syncthreads();
        const int jmax = (kt == qtile) ? r : 63;
        int j = 0;
        for (; j + 1 <= jmax; j += 2) {
            int jm = j + hf;
            float s = __bfloat162float(Sc[sbase + (size_t)(kt * 64 + jm) * 64 + r]) * 0.125f;
            float p = bf16r(__fdiv_rn(exp_acc(s - m), l));
            float po = __shfl_xor_sync(pair_mask, p, 1);
            float p_even = hf ? po : p;
            float p_odd  = hf ? p  : po;
            u64 pp0 = pack2(p_even, p_even);
            u64 pp1 = pack2(p_odd,  p_odd);
            const float* v0 = &Vs[j][hf * 32];
            const float* v1 = &Vs[j + 1][hf * 32];
#pragma unroll
            for (int i = 0; i < 16; i++) {
                o2[i] = fma2(pp0, *(const u64*)&v0[i * 2], o2[i]);
                o2[i] = fma2(pp1, *(const u64*)&v1[i * 2], o2[i]);
            }
        }
        if (j <= jmax) {
            float s = __bfloat162float(Sc[sbase + (size_t)(kt * 64 + j) * 64 + r]) * 0.125f;
            float p = bf16r(__fdiv_rn(exp_acc(s - m), l));
            u64 pp = pack2(p, p);
            const float* vr = &Vs[j][hf * 32];
#pragma unroll
            for (int i = 0; i < 16; i++)
                o2[i] = fma2(pp, *(const u64*)&vr[i * 2], o2[i]);
        }
    }

    float* op = O + (size_t)t * D_MODEL + h * HD + hf * 32;
#pragma unroll
    for (int i = 0; i < 16; i++) {
        float lo, hi;
        unpack2(o2[i], lo, hi);
        op[i * 2]     = bf16r(lo);
        op[i * 2 + 1] = bf16r(hi);
    }
}

// ---------------- host launcher ----------------------------------------------
extern "C" void kernel_launch(void* const* d_in, const int* in_sizes, int n_in,
                              void* d_out, int out_size) {
    (void)out_size;

    const float *x = 0, *w_o = 0, *scale_q = 0, *scale_kv = 0;
    const float *p524[2] = {0, 0}, *p262[3] = {0, 0, 0}, *p65[2] = {0, 0};
    int n524 = 0, n262 = 0, n65 = 0;
    for (int i = 0; i < n_in; i++) {
        switch (in_sizes[i]) {
            case 4194304: x = (const float*)d_in[i]; break;
            case 1048576: w_o = (const float*)d_in[i]; break;
            case 512:     scale_q  = (const float*)d_in[i]; break;
            case 256:     scale_kv = (const float*)d_in[i]; break;
            case 524288:  if (n524 < 2) p524[n524++] = (const float*)d_in[i]; break;
            case 262144:  if (n262 < 3) p262[n262++] = (const float*)d_in[i]; break;
            case 65536:   if (n65 < 2)  p65[n65++]  = (const float*)d_in[i]; break;
            default: break;
        }
    }
    const float* w_dq  = p524[0];
    const float* w_uq  = p524[1];
    const float* sin_p = p262[0];
    const float* cos_p = p262[1];
    const float* w_dkv = p262[2];
    const float* w_uk  = p65[0];
    const float* w_uv  = p65[1];
    float* out = (float*)d_out;

    float *qlat_raw, *qlat, *qb, *q_ro, *kvraw, *kvlat, *kb, *k_ro, *vb, *attn;
    __nv_bfloat16* scores;
    cudaGetSymbolAddress((void**)&qlat_raw, g_qlat_raw);
    cudaGetSymbolAddress((void**)&qlat,     g_qlat);
    cudaGetSymbolAddress((void**)&qb,       g_q);
    cudaGetSymbolAddress((void**)&q_ro,     g_q_ro);
    cudaGetSymbolAddress((void**)&kvraw,    g_kvraw);
    cudaGetSymbolAddress((void**)&kvlat,    g_kvlat);
    cudaGetSymbolAddress((void**)&kb,       g_k);
    cudaGetSymbolAddress((void**)&k_ro,     g_k_ro);
    cudaGetSymbolAddress((void**)&vb,       g_v);
    cudaGetSymbolAddress((void**)&attn,     g_attn);
    cudaGetSymbolAddress((void**)&scores,   g_scores);

    auto blocks = [](long long n) { return (int)((n + 255) / 256); };

    // q path (reads f32 inputs directly — values are exactly bf16-valued)
    gemm_ffma2<<<dim3(QL / 64, T_SEQ / 128), 256>>>(x, w_dq, qlat_raw,
                                                    T_SEQ, QL, D_MODEL);
    rmsnorm_kernel<<<T_SEQ, 256>>>(qlat_raw, scale_q, qlat, QL);
    gemm_ffma2<<<dim3((NH * HD) / 64, T_SEQ / 128), 256>>>(qlat, w_uq, qb,
                                                           T_SEQ, NH * HD, QL);

    // kv path
    gemm_ffma2<<<dim3(KVL / 64, T_SEQ / 128), 256>>>(x, w_dkv, kvraw,
                                                     T_SEQ, KVL, D_MODEL);
    rmsnorm_kernel<<<T_SEQ, 256>>>(kvraw, scale_kv, kvlat, KVL);
    gemm_ffma2<<<dim3((NKV * HD) / 64, T_SEQ / 128), 256>>>(kvlat, w_uk, kb,
                                                            T_SEQ, NKV * HD, KVL);
    gemm_ffma2<<<dim3((NKV * HD) / 64, T_SEQ / 128), 256>>>(kvlat, w_uv, vb,
                                                            T_SEQ, NKV * HD, KVL);

    // rope
    rope_kernel<<<blocks((long long)T_SEQ * NH * HD), 256>>>(qb, sin_p, cos_p, q_ro, NH);
    rope_kernel<<<blocks((long long)T_SEQ * NKV * HD), 256>>>(kb, sin_p, cos_p, k_ro, NKV);

    // attention
    attn_kernel<<<dim3(T_SEQ / 64, NH), 128>>>(q_ro, k_ro, vb, attn, scores);

    // final projection
    gemm_ffma2<<<dim3(D_MODEL / 64, T_SEQ / 128), 256>>>(attn, w_o, out,
                                                         T_SEQ, D_MODEL, D_MODEL);
}

// round 10
// speedup vs baseline: 7.1434x; 1.1663x over previous
#include <cuda_runtime.h>
#include <cuda_bf16.h>
#include <cstdint>

#define T_SEQ   4096
#define D_MODEL 1024
#define NH      16
#define NKV     4
#define HD      64
#define QL      512
#define KVL     256
#define NT      64
#define TRI_ENT 8519680                 // 2080 tile-pairs * 4096 entries per head

// ---------------- scratch (device globals; all f32, values bf16-rounded) -----
static __device__ float g_qlat_raw[T_SEQ * QL];
static __device__ float g_qlat    [T_SEQ * QL];
static __device__ float g_q       [T_SEQ * NH * HD];
static __device__ float g_q_ro    [T_SEQ * NH * HD];
static __device__ float g_kvraw   [T_SEQ * KVL];
static __device__ float g_kvlat   [T_SEQ * KVL];
static __device__ float g_k       [T_SEQ * NKV * HD];
static __device__ float g_k_ro    [T_SEQ * NKV * HD];
static __device__ float g_v       [T_SEQ * NKV * HD];
static __device__ float g_attn    [T_SEQ * D_MODEL];

// causal-packed raw scores: per head, per qtile, [key j][row r], bf16(q.k)
static __device__ __nv_bfloat16 g_scores[(size_t)NH * TRI_ENT];

// ---------------- helpers -----------------------------------------------------
__device__ __forceinline__ float bf16r(float x) {
    return __bfloat162float(__float2bfloat16(x));
}

typedef unsigned long long u64;

__device__ __forceinline__ u64 pack2(float lo, float hi) {
    u64 r;
    asm("mov.b64 %0, {%1, %2};" : "=l"(r) : "f"(lo), "f"(hi));
    return r;
}
__device__ __forceinline__ void unpack2(u64 v, float& lo, float& hi) {
    asm("mov.b64 {%0, %1}, %2;" : "=f"(lo), "=f"(hi) : "l"(v));
}
__device__ __forceinline__ u64 d2u(double d) {
    return (u64)__double_as_longlong(d);   // free reinterpret: reg pair IS u64
}
// packed IEEE f32 FMA (FFMA2) — per-element identical to scalar fmaf
__device__ __forceinline__ u64 fma2(u64 a, u64 b, u64 c) {
    u64 d;
    asm("fma.rn.f32x2 %0, %1, %2, %3;" : "=l"(d) : "l"(a), "l"(b), "l"(c));
    return d;
}

// Deterministic ~1-ulp exp, fmaf-only (identical since round 7).
__device__ __forceinline__ float exp_acc(float x) {
    x = fmaxf(x, -87.0f);
    float n = rintf(x * 1.44269504088896340736f);
    float r = fmaf(n, -0.693145751953125f, x);
    r = fmaf(n, -1.42860677e-06f, r);
    float p = 1.9841269841e-04f;
    p = fmaf(p, r, 1.3888888889e-03f);
    p = fmaf(p, r, 8.3333333333e-03f);
    p = fmaf(p, r, 4.1666666667e-02f);
    p = fmaf(p, r, 1.6666666667e-01f);
    p = fmaf(p, r, 0.5f);
    p = fmaf(p, r, 1.0f);
    p = fmaf(p, r, 1.0f);
    int in = (int)n;
    return p * __int_as_float((in + 127) << 23);
}

// ---------------- GEMM: 128x64 tile, BK=32, row-pair FFMA2 core --------------
// A smem transposed [kk][row]: adjacent rows form the u64 FFMA2 operand with
// zero packing. Each output element keeps its own ascending-k chain ->
// bit-identical to rounds 8/9.
__global__ void __launch_bounds__(256, 2)
gemm_ffma2(const float* __restrict__ A,
           const float* __restrict__ B,
           float* __restrict__ C,
           int M, int N, int K) {
    __shared__ float As[32][136];   // [kk][row]; 136: 16B-aligned rows, low conflict
    __shared__ float Bs[32][68];    // [kk][col]

    const int tid = threadIdx.x;
    const int tx = tid & 15;        // 4 cols
    const int ty = tid >> 4;        // 8 rows = 4 row-pairs
    const int row0 = blockIdx.y * 128;
    const int col0 = blockIdx.x * 64;

    const int a_row  = tid & 127;   // conflict-free store pattern
    const int a_half = tid >> 7;    // k half
    const int b_row  = tid >> 3;
    const int b_col  = (tid & 7) * 8;

    u64 acc2[4][4];                 // [row-pair][col]
#pragma unroll
    for (int p = 0; p < 4; p++)
#pragma unroll
        for (int j = 0; j < 4; j++) acc2[p][j] = 0ull;

    for (int k0 = 0; k0 < K; k0 += 32) {
        {
            const float* ap = A + (size_t)(row0 + a_row) * K + k0 + a_half * 16;
            float av[16];
#pragma unroll
            for (int u = 0; u < 4; u++)
                *(float4*)&av[u * 4] = ((const float4*)ap)[u];
#pragma unroll
            for (int u = 0; u < 16; u++)
                As[a_half * 16 + u][a_row] = av[u];
        }
        {
            const float* bp = B + (size_t)(k0 + b_row) * N + col0 + b_col;
            *(float4*)&Bs[b_row][b_col]     = ((const float4*)bp)[0];
            *(float4*)&Bs[b_row][b_col + 4] = ((const float4*)bp)[1];
        }
        __syncthreads();

#pragma unroll 4
        for (int kk = 0; kk < 32; kk++) {
            float4 bf = *(const float4*)&Bs[kk][tx * 4];
            u64 b0 = pack2(bf.x, bf.x);
            u64 b1 = pack2(bf.y, bf.y);
            u64 b2 = pack2(bf.z, bf.z);
            u64 b3 = pack2(bf.w, bf.w);
            double2 a01 = *(const double2*)&As[kk][ty * 8];
            double2 a23 = *(const double2*)&As[kk][ty * 8 + 4];
            u64 ap_[4] = { d2u(a01.x), d2u(a01.y), d2u(a23.x), d2u(a23.y) };
#pragma unroll
            for (int p = 0; p < 4; p++) {
                acc2[p][0] = fma2(ap_[p], b0, acc2[p][0]);
                acc2[p][1] = fma2(ap_[p], b1, acc2[p][1]);
                acc2[p][2] = fma2(ap_[p], b2, acc2[p][2]);
                acc2[p][3] = fma2(ap_[p], b3, acc2[p][3]);
            }
        }
        __syncthreads();
    }

#pragma unroll
    for (int p = 0; p < 4; p++) {
        float lo0, hi0, lo1, hi1, lo2, hi2, lo3, hi3;
        unpack2(acc2[p][0], lo0, hi0);
        unpack2(acc2[p][1], lo1, hi1);
        unpack2(acc2[p][2], lo2, hi2);
        unpack2(acc2[p][3], lo3, hi3);
        float4 ve = make_float4(bf16r(lo0), bf16r(lo1), bf16r(lo2), bf16r(lo3));
        float4 vo = make_float4(bf16r(hi0), bf16r(hi1), bf16r(hi2), bf16r(hi3));
        *(float4*)&C[(size_t)(row0 + ty * 8 + 2 * p)     * N + col0 + tx * 4] = ve;
        *(float4*)&C[(size_t)(row0 + ty * 8 + 2 * p + 1) * N + col0 + tx * 4] = vo;
    }
}

// ---------------- RMSNorm (same FP ops) ---------------------------------------
__global__ void rmsnorm_kernel(const float* __restrict__ in,
                               const float* __restrict__ scale,
                               float* __restrict__ out,
                               int cols) {
    const int row = blockIdx.x;
    const int tid = threadIdx.x;
    const float* x = in + (size_t)row * cols;
    float* y = out + (size_t)row * cols;

    __shared__ float red[256];
    float s = 0.0f;
    for (int c = tid; c < cols; c += 256) {
        float v = x[c];
        s = fmaf(v, v, s);
    }
    red[tid] = s;
    __syncthreads();
    for (int off = 128; off > 0; off >>= 1) {
        if (tid < off) red[tid] += red[tid + off];
        __syncthreads();
    }
    float rms = __fsqrt_rn(red[0] / (float)cols + 1e-6f);
    for (int c = tid; c < cols; c += 256)
        y[c] = bf16r(__fdiv_rn(x[c], rms) * scale[c]);
}

// ---------------- RoPE (same FP ops) -------------------------------------------
__global__ void rope_kernel(const float* __restrict__ in,
                            const float* __restrict__ sin_t,
                            const float* __restrict__ cos_t,
                            float* __restrict__ out,
                            int heads) {
    int idx = blockIdx.x * blockDim.x + threadIdx.x;
    int total = T_SEQ * heads * HD;
    if (idx >= total) return;
    int d = idx & 63;
    int t = (idx >> 6) / heads;
    float xv = in[idx];
    float rot = (d < 32) ? -in[idx + 32] : in[idx - 32];
    float r1 = bf16r(xv * cos_t[t * HD + d]);
    float r2 = bf16r(rot * sin_t[t * HD + d]);
    out[idx] = bf16r(r1 + r2);
}

// ---------------- causal attention (FP ops identical to rounds 8/9) -----------
__global__ void __launch_bounds__(128, 5)
attn_kernel(const float* __restrict__ Q,
            const float* __restrict__ Kc,
            const float* __restrict__ Vc,
            float* __restrict__ O,
            __nv_bfloat16* __restrict__ Sc) {
    __shared__ float Ks[64][64];
    __shared__ float Vs[64][64];

    const int qtile = (int)gridDim.x - 1 - (int)blockIdx.x;   // heavy blocks first
    const int h = blockIdx.y;
    const int hk = h >> 2;
    const int tid = threadIdx.x;
    const int r = tid >> 1;
    const int hf = tid & 1;
    const int t = qtile * 64 + r;
    const unsigned pair_mask = 0x3u << ((tid & 31) & ~1);

    const size_t sbase = (size_t)h * TRI_ENT +
                         (size_t)qtile * (qtile + 1) / 2 * 4096;

    float4 q4[8];
    {
        const float* qp = Q + (size_t)t * D_MODEL + h * HD + hf * 32;
#pragma unroll
        for (int u = 0; u < 8; u++) q4[u] = ((const float4*)qp)[u];
    }

    const int ldj = tid >> 1;
    const int ldh = tid & 1;

    auto load_k = [&](int kt) {
        const float* kg = Kc + (size_t)(kt * 64 + ldj) * (NKV * HD) + hk * HD + ldh * 32;
        float4* dst = (float4*)&Ks[ldj][ldh * 32];
#pragma unroll
        for (int u = 0; u < 8; u++) dst[u] = ((const float4*)kg)[u];
    };
    auto load_v = [&](int kt) {
        const float* vg = Vc + (size_t)(kt * 64 + ldj) * (NKV * HD) + hk * HD + ldh * 32;
        float4* dst = (float4*)&Vs[ldj][ldh * 32];
#pragma unroll
        for (int u = 0; u < 8; u++) dst[u] = ((const float4*)vg)[u];
    };

    // ---- pass 1: QK once (float4 K loads, same ascending-i chain), store ----
    float m = -1e30f;
    for (int kt = 0; kt <= qtile; kt++) {
        __syncthreads();
        load_k(kt);
        __syncthreads();
        const int jmax = (kt == qtile) ? r : 63;
        for (int j = 0; j <= jmax; j++) {
            const float4* kr4 = (const float4*)&Ks[j][hf * 32];
            float part = 0.0f;
#pragma unroll
            for (int u = 0; u < 8; u++) {
                float4 kv = kr4[u];
                part = fmaf(q4[u].x, kv.x, part);
                part = fmaf(q4[u].y, kv.y, part);
                part = fmaf(q4[u].z, kv.z, part);
                part = fmaf(q4[u].w, kv.w, part);
            }
            float sum = part + __shfl_xor_sync(pair_mask, part, 1);
            __nv_bfloat16 sb = __float2bfloat16(sum);
            if (hf == 0) Sc[sbase + (size_t)(kt * 64 + j) * 64 + r] = sb;
            float s = __bfloat162float(sb) * 0.125f;
            m = fmaxf(m, s);
        }
    }
    __syncthreads();

    // ---- pass 2: l = sum exp(s - m), pairwise exp dedup, ascending order ----
    float l = 0.0f;
    for (int kt = 0; kt <= qtile; kt++) {
        const int jmax = (kt == qtile) ? r : 63;
        int j = 0;
        for (; j + 1 <= jmax; j += 2) {
            int jm = j + hf;
            float s = __bfloat162float(Sc[sbase + (size_t)(kt * 64 + jm) * 64 + r]) * 0.125f;
            float e = exp_acc(s - m);
            float eo = __shfl_xor_sync(pair_mask, e, 1);
            float e_even = hf ? eo : e;
            float e_odd  = hf ? e  : eo;
            l += e_even;
            l += e_odd;
        }
        if (j <= jmax) {
            float s = __bfloat162float(Sc[sbase + (size_t)(kt * 64 + j) * 64 + r]) * 0.125f;
            l += exp_acc(s - m);
        }
    }

    // ---- pass 3: probs pairwise, PV FFMA2, double2 V loads (free u64) -------
    u64 o2[16];
#pragma unroll
    for (int i = 0; i < 16; i++) o2[i] = 0ull;

    for (int kt = 0; kt <= qtile; kt++) {
        __syncthreads();
        load_v(kt);
        __syncthreads();
        const int jmax = (kt == qtile) ? r : 63;
        int j = 0;
        for (; j + 1 <= jmax; j += 2) {
            int jm = j + hf;
            float s = __bfloat162float(Sc[sbase + (size_t)(kt * 64 + jm) * 64 + r]) * 0.125f;
            float p = bf16r(__fdiv_rn(exp_acc(s - m), l));
            float po = __shfl_xor_sync(pair_mask, p, 1);
            float p_even = hf ? po : p;
            float p_odd  = hf ? p  : po;
            u64 pp0 = pack2(p_even, p_even);
            u64 pp1 = pack2(p_odd,  p_odd);
            const double2* v0d = (const double2*)&Vs[j][hf * 32];
            const double2* v1d = (const double2*)&Vs[j + 1][hf * 32];
#pragma unroll
            for (int u = 0; u < 8; u++) {
                double2 dv0 = v0d[u];
                double2 dv1 = v1d[u];
                o2[2 * u]     = fma2(pp0, d2u(dv0.x), o2[2 * u]);
                o2[2 * u + 1] = fma2(pp0, d2u(dv0.y), o2[2 * u + 1]);
                o2[2 * u]     = fma2(pp1, d2u(dv1.x), o2[2 * u]);
                o2[2 * u + 1] = fma2(pp1, d2u(dv1.y), o2[2 * u + 1]);
            }
        }
        if (j <= jmax) {
            float s = __bfloat162float(Sc[sbase + (size_t)(kt * 64 + j) * 64 + r]) * 0.125f;
            float p = bf16r(__fdiv_rn(exp_acc(s - m), l));
            u64 pp = pack2(p, p);
            const double2* vd = (const double2*)&Vs[j][hf * 32];
#pragma unroll
            for (int u = 0; u < 8; u++) {
                double2 dv = vd[u];
                o2[2 * u]     = fma2(pp, d2u(dv.x), o2[2 * u]);
                o2[2 * u + 1] = fma2(pp, d2u(dv.y), o2[2 * u + 1]);
            }
        }
    }

    float* op = O + (size_t)t * D_MODEL + h * HD + hf * 32;
#pragma unroll
    for (int i = 0; i < 16; i++) {
        float lo, hi;
        unpack2(o2[i], lo, hi);
        op[i * 2]     = bf16r(lo);
        op[i * 2 + 1] = bf16r(hi);
    }
}

// ---------------- host launcher ----------------------------------------------
extern "C" void kernel_launch(void* const* d_in, const int* in_sizes, int n_in,
                              void* d_out, int out_size) {
    (void)out_size;

    const float *x = 0, *w_o = 0, *scale_q = 0, *scale_kv = 0;
    const float *p524[2] = {0, 0}, *p262[3] = {0, 0, 0}, *p65[2] = {0, 0};
    int n524 = 0, n262 = 0, n65 = 0;
    for (int i = 0; i < n_in; i++) {
        switch (in_sizes[i]) {
            case 4194304: x = (const float*)d_in[i]; break;
            case 1048576: w_o = (const float*)d_in[i]; break;
            case 512:     scale_q  = (const float*)d_in[i]; break;
            case 256:     scale_kv = (const float*)d_in[i]; break;
            case 524288:  if (n524 < 2) p524[n524++] = (const float*)d_in[i]; break;
            case 262144:  if (n262 < 3) p262[n262++] = (const float*)d_in[i]; break;
            case 65536:   if (n65 < 2)  p65[n65++]  = (const float*)d_in[i]; break;
            default: break;
        }
    }
    const float* w_dq  = p524[0];
    const float* w_uq  = p524[1];
    const float* sin_p = p262[0];
    const float* cos_p = p262[1];
    const float* w_dkv = p262[2];
    const float* w_uk  = p65[0];
    const float* w_uv  = p65[1];
    float* out = (float*)d_out;

    float *qlat_raw, *qlat, *qb, *q_ro, *kvraw, *kvlat, *kb, *k_ro, *vb, *attn;
    __nv_bfloat16* scores;
    cudaGetSymbolAddress((void**)&qlat_raw, g_qlat_raw);
    cudaGetSymbolAddress((void**)&qlat,     g_qlat);
    cudaGetSymbolAddress((void**)&qb,       g_q);
    cudaGetSymbolAddress((void**)&q_ro,     g_q_ro);
    cudaGetSymbolAddress((void**)&kvraw,    g_kvraw);
    cudaGetSymbolAddress((void**)&kvlat,    g_kvlat);
    cudaGetSymbolAddress((void**)&kb,       g_k);
    cudaGetSymbolAddress((void**)&k_ro,     g_k_ro);
    cudaGetSymbolAddress((void**)&vb,       g_v);
    cudaGetSymbolAddress((void**)&attn,     g_attn);
    cudaGetSymbolAddress((void**)&scores,   g_scores);

    auto blocks = [](long long n) { return (int)((n + 255) / 256); };

    // q path
    gemm_ffma2<<<dim3(QL / 64, T_SEQ / 128), 256>>>(x, w_dq, qlat_raw,
                                                    T_SEQ, QL, D_MODEL);
    rmsnorm_kernel<<<T_SEQ, 256>>>(qlat_raw, scale_q, qlat, QL);
    gemm_ffma2<<<dim3((NH * HD) / 64, T_SEQ / 128), 256>>>(qlat, w_uq, qb,
                                                           T_SEQ, NH * HD, QL);

    // kv path
    gemm_ffma2<<<dim3(KVL / 64, T_SEQ / 128), 256>>>(x, w_dkv, kvraw,
                                                     T_SEQ, KVL, D_MODEL);
    rmsnorm_kernel<<<T_SEQ, 256>>>(kvraw, scale_kv, kvlat, KVL);
    gemm_ffma2<<<dim3((NKV * HD) / 64, T_SEQ / 128), 256>>>(kvlat, w_uk, kb,
                                                            T_SEQ, NKV * HD, KVL);
    gemm_ffma2<<<dim3((NKV * HD) / 64, T_SEQ / 128), 256>>>(kvlat, w_uv, vb,
                                                            T_SEQ, NKV * HD, KVL);

    // rope
    rope_kernel<<<blocks((long long)T_SEQ * NH * HD), 256>>>(qb, sin_p, cos_p, q_ro, NH);
    rope_kernel<<<blocks((long long)T_SEQ * NKV * HD), 256>>>(kb, sin_p, cos_p, k_ro, NKV);

    // attention
    attn_kernel<<<dim3(T_SEQ / 64, NH), 128>>>(q_ro, k_ro, vb, attn, scores);

    // final projection
    gemm_ffma2<<<dim3(D_MODEL / 64, T_SEQ / 128), 256>>>(attn, w_o, out,
                                                         T_SEQ, D_MODEL, D_MODEL);
}

// round 11
// speedup vs baseline: 10.6643x; 1.4929x over previous
#include <cuda_runtime.h>
#include <cuda_bf16.h>
#include <cstdint>

#define T_SEQ   4096
#define D_MODEL 1024
#define NH      16
#define NKV     4
#define HD      64
#define QL      512
#define KVL     256
#define TRI_ENT 8519680                 // 2080 tile-pairs * 4096 entries per head

// ---------------- scratch (device globals; all f32, values bf16-rounded) -----
static __device__ float g_qlat_raw[T_SEQ * QL];
static __device__ float g_qlat    [T_SEQ * QL];
static __device__ float g_q       [T_SEQ * NH * HD];
static __device__ float g_q_ro    [T_SEQ * NH * HD];
static __device__ float g_kvraw   [T_SEQ * KVL];
static __device__ float g_kvlat   [T_SEQ * KVL];
static __device__ float g_k       [T_SEQ * NKV * HD];
static __device__ float g_k_ro    [T_SEQ * NKV * HD];
static __device__ float g_v       [T_SEQ * NKV * HD];
static __device__ float g_attn    [T_SEQ * D_MODEL];

// causal-packed raw scores: per head, per qtile, [key j][row r], bf16(q.k)
static __device__ __nv_bfloat16 g_scores[(size_t)NH * TRI_ENT];

// ---------------- helpers -----------------------------------------------------
__device__ __forceinline__ float bf16r(float x) {
    return __bfloat162float(__float2bfloat16(x));
}

typedef unsigned long long u64;

__device__ __forceinline__ u64 pack2(float lo, float hi) {
    u64 r;
    asm("mov.b64 %0, {%1, %2};" : "=l"(r) : "f"(lo), "f"(hi));
    return r;
}
__device__ __forceinline__ void unpack2(u64 v, float& lo, float& hi) {
    asm("mov.b64 {%0, %1}, %2;" : "=f"(lo), "=f"(hi) : "l"(v));
}
__device__ __forceinline__ u64 d2u(double d) {
    return (u64)__double_as_longlong(d);
}
// packed IEEE f32 FMA (FFMA2) — per-element identical to scalar fmaf
__device__ __forceinline__ u64 fma2(u64 a, u64 b, u64 c) {
    u64 d;
    asm("fma.rn.f32x2 %0, %1, %2, %3;" : "=l"(d) : "l"(a), "l"(b), "l"(c));
    return d;
}

// Deterministic ~1-ulp exp, fmaf-only (identical since round 7).
__device__ __forceinline__ float exp_acc(float x) {
    x = fmaxf(x, -87.0f);
    float n = rintf(x * 1.44269504088896340736f);
    float r = fmaf(n, -0.693145751953125f, x);
    r = fmaf(n, -1.42860677e-06f, r);
    float p = 1.9841269841e-04f;
    p = fmaf(p, r, 1.3888888889e-03f);
    p = fmaf(p, r, 8.3333333333e-03f);
    p = fmaf(p, r, 4.1666666667e-02f);
    p = fmaf(p, r, 1.6666666667e-01f);
    p = fmaf(p, r, 0.5f);
    p = fmaf(p, r, 1.0f);
    p = fmaf(p, r, 1.0f);
    int in = (int)n;
    return p * __int_as_float((in + 127) << 23);
}

// ---------------- GEMM: 64x64 tile, BK=32, 128 threads, FFMA2 core -----------
// Each output element's k-chain strictly ascending -> bit-identical to R8-R10.
__global__ void __launch_bounds__(128, 4)
gemm_ffma2(const float* __restrict__ A,
           const float* __restrict__ B,
           float* __restrict__ C,
           int M, int N, int K) {
    __shared__ float As[32][68];   // [kk][row] transposed
    __shared__ float Bs[32][68];   // [kk][col]

    const int tid = threadIdx.x;
    const int tx = tid & 15;        // 4 cols
    const int ty = tid >> 4;        // 0..7 -> 8 rows = 4 row-pairs
    const int row0 = blockIdx.y * 64;
    const int col0 = blockIdx.x * 64;

    const int a_row  = tid & 63;
    const int a_half = tid >> 6;    // k half (16 each)
    const int b_row  = tid >> 2;    // 0..31
    const int b_col  = (tid & 3) * 16;

    u64 acc2[4][4];
#pragma unroll
    for (int p = 0; p < 4; p++)
#pragma unroll
        for (int j = 0; j < 4; j++) acc2[p][j] = 0ull;

    for (int k0 = 0; k0 < K; k0 += 32) {
        {
            const float* ap = A + (size_t)(row0 + a_row) * K + k0 + a_half * 16;
            float av[16];
#pragma unroll
            for (int u = 0; u < 4; u++)
                *(float4*)&av[u * 4] = ((const float4*)ap)[u];
#pragma unroll
            for (int u = 0; u < 16; u++)
                As[a_half * 16 + u][a_row] = av[u];
        }
        {
            const float* bp = B + (size_t)(k0 + b_row) * N + col0 + b_col;
#pragma unroll
            for (int u = 0; u < 4; u++)
                *(float4*)&Bs[b_row][b_col + u * 4] = ((const float4*)bp)[u];
        }
        __syncthreads();

#pragma unroll 4
        for (int kk = 0; kk < 32; kk++) {
            float4 bf = *(const float4*)&Bs[kk][tx * 4];
            u64 b0 = pack2(bf.x, bf.x);
            u64 b1 = pack2(bf.y, bf.y);
            u64 b2 = pack2(bf.z, bf.z);
            u64 b3 = pack2(bf.w, bf.w);
            double2 a01 = *(const double2*)&As[kk][ty * 8];
            double2 a23 = *(const double2*)&As[kk][ty * 8 + 4];
            u64 ap_[4] = { d2u(a01.x), d2u(a01.y), d2u(a23.x), d2u(a23.y) };
#pragma unroll
            for (int p = 0; p < 4; p++) {
                acc2[p][0] = fma2(ap_[p], b0, acc2[p][0]);
                acc2[p][1] = fma2(ap_[p], b1, acc2[p][1]);
                acc2[p][2] = fma2(ap_[p], b2, acc2[p][2]);
                acc2[p][3] = fma2(ap_[p], b3, acc2[p][3]);
            }
        }
        __syncthreads();
    }

#pragma unroll
    for (int p = 0; p < 4; p++) {
        float lo0, hi0, lo1, hi1, lo2, hi2, lo3, hi3;
        unpack2(acc2[p][0], lo0, hi0);
        unpack2(acc2[p][1], lo1, hi1);
        unpack2(acc2[p][2], lo2, hi2);
        unpack2(acc2[p][3], lo3, hi3);
        float4 ve = make_float4(bf16r(lo0), bf16r(lo1), bf16r(lo2), bf16r(lo3));
        float4 vo = make_float4(bf16r(hi0), bf16r(hi1), bf16r(hi2), bf16r(hi3));
        *(float4*)&C[(size_t)(row0 + ty * 8 + 2 * p)     * N + col0 + tx * 4] = ve;
        *(float4*)&C[(size_t)(row0 + ty * 8 + 2 * p + 1) * N + col0 + tx * 4] = vo;
    }
}

// ---------------- RMSNorm (same FP ops) ---------------------------------------
__global__ void rmsnorm_kernel(const float* __restrict__ in,
                               const float* __restrict__ scale,
                               float* __restrict__ out,
                               int cols) {
    const int row = blockIdx.x;
    const int tid = threadIdx.x;
    const float* x = in + (size_t)row * cols;
    float* y = out + (size_t)row * cols;

    __shared__ float red[256];
    float s = 0.0f;
    for (int c = tid; c < cols; c += 256) {
        float v = x[c];
        s = fmaf(v, v, s);
    }
    red[tid] = s;
    __syncthreads();
    for (int off = 128; off > 0; off >>= 1) {
        if (tid < off) red[tid] += red[tid + off];
        __syncthreads();
    }
    float rms = __fsqrt_rn(red[0] / (float)cols + 1e-6f);
    for (int c = tid; c < cols; c += 256)
        y[c] = bf16r(__fdiv_rn(x[c], rms) * scale[c]);
}

// ---------------- RoPE (same FP ops) -------------------------------------------
__global__ void rope_kernel(const float* __restrict__ in,
                            const float* __restrict__ sin_t,
                            const float* __restrict__ cos_t,
                            float* __restrict__ out,
                            int heads) {
    int idx = blockIdx.x * blockDim.x + threadIdx.x;
    int total = T_SEQ * heads * HD;
    if (idx >= total) return;
    int d = idx & 63;
    int t = (idx >> 6) / heads;
    float xv = in[idx];
    float rot = (d < 32) ? -in[idx + 32] : in[idx - 32];
    float r1 = bf16r(xv * cos_t[t * HD + d]);
    float r2 = bf16r(rot * sin_t[t * HD + d]);
    out[idx] = bf16r(r1 + r2);
}

// ---------------- causal attention: register-tiled QK/PV -----------------------
// FP values/order identical to R8-R10 (see theory). 128 threads per (qtile,h).
__global__ void __launch_bounds__(128, 4)
attn_kernel(const float* __restrict__ Q,
            const float* __restrict__ Kc,
            const float* __restrict__ Vc,
            float* __restrict__ O,
            __nv_bfloat16* __restrict__ Sc) {
    __shared__ float QP[64][68];   // pass1: Qs[i][row]; pass3: Ps[row][j]
    __shared__ float KV[64][68];   // pass1: Ks[i][key]; pass3: Vs[j][dim]
    __shared__ float m_s[64];
    __shared__ float l_s[64];

    const int qtile = (int)gridDim.x - 1 - (int)blockIdx.x;   // heavy first
    const int h = blockIdx.y;
    const int hk = h >> 2;
    const int tid = threadIdx.x;
    const size_t sbase = (size_t)h * TRI_ENT +
                         (size_t)qtile * (qtile + 1) / 2 * 4096;

    const int rg = tid >> 3;    // 0..15 -> 4 rows each
    const int kg = tid & 7;     // 0..7  -> 8 keys/dims each

    // ---- load Q tile transposed: QP[i][row] ----
    {
        const int r_ld = tid >> 1, dh = tid & 1;
        const float* qp = Q + (size_t)(qtile * 64 + r_ld) * D_MODEL + h * HD + dh * 32;
        float qv[32];
#pragma unroll
        for (int u = 0; u < 8; u++)
            *(float4*)&qv[u * 4] = ((const float4*)qp)[u];
#pragma unroll
        for (int u = 0; u < 32; u++)
            QP[dh * 32 + u][r_ld] = qv[u];
    }

    float mreg[4] = { -1e30f, -1e30f, -1e30f, -1e30f };

    // ================= pass 1: QK GEMM, store bf16 scores, exact max =========
    for (int kt = 0; kt <= qtile; kt++) {
        __syncthreads();
        {
            const int key = tid >> 1, dh = tid & 1;
            const float* kp = Kc + (size_t)(kt * 64 + key) * (NKV * HD) + hk * HD + dh * 32;
            float kv[32];
#pragma unroll
            for (int u = 0; u < 8; u++)
                *(float4*)&kv[u * 4] = ((const float4*)kp)[u];
#pragma unroll
            for (int u = 0; u < 32; u++)
                KV[dh * 32 + u][key] = kv[u];
        }
        __syncthreads();

        u64 alo[4][4], ahi[4][4];
#pragma unroll
        for (int a = 0; a < 4; a++)
#pragma unroll
            for (int b = 0; b < 4; b++) { alo[a][b] = 0ull; ahi[a][b] = 0ull; }

#pragma unroll 8
        for (int i = 0; i < 32; i++) {
            float4 qv = *(const float4*)&QP[i][rg * 4];
            double2 ka = *(const double2*)&KV[i][kg * 8];
            double2 kb = *(const double2*)&KV[i][kg * 8 + 4];
            u64 kp_[4] = { d2u(ka.x), d2u(ka.y), d2u(kb.x), d2u(kb.y) };
            u64 q_[4] = { pack2(qv.x, qv.x), pack2(qv.y, qv.y),
                          pack2(qv.z, qv.z), pack2(qv.w, qv.w) };
#pragma unroll
            for (int a = 0; a < 4; a++)
#pragma unroll
                for (int b = 0; b < 4; b++)
                    alo[a][b] = fma2(q_[a], kp_[b], alo[a][b]);
        }
#pragma unroll 8
        for (int i = 32; i < 64; i++) {
            float4 qv = *(const float4*)&QP[i][rg * 4];
            double2 ka = *(const double2*)&KV[i][kg * 8];
            double2 kb = *(const double2*)&KV[i][kg * 8 + 4];
            u64 kp_[4] = { d2u(ka.x), d2u(ka.y), d2u(kb.x), d2u(kb.y) };
            u64 q_[4] = { pack2(qv.x, qv.x), pack2(qv.y, qv.y),
                          pack2(qv.z, qv.z), pack2(qv.w, qv.w) };
#pragma unroll
            for (int a = 0; a < 4; a++)
#pragma unroll
                for (int b = 0; b < 4; b++)
                    ahi[a][b] = fma2(q_[a], kp_[b], ahi[a][b]);
        }

        // epilogue: sum = lo + hi (same operands as old part+shfl), bf16, store
        float scv[8][4];   // [key][row]
#pragma unroll
        for (int b = 0; b < 4; b++)
#pragma unroll
            for (int a = 0; a < 4; a++) {
                float l0, l1, h0, h1;
                unpack2(alo[a][b], l0, l1);
                unpack2(ahi[a][b], h0, h1);
                scv[b * 2][a]     = l0 + h0;
                scv[b * 2 + 1][a] = l1 + h1;
            }
#pragma unroll
        for (int jj = 0; jj < 8; jj++) {
            int j = kg * 8 + jj;
            int gj = kt * 64 + j;
            __nv_bfloat162 pa = __floats2bfloat162_rn(scv[jj][0], scv[jj][1]);
            __nv_bfloat162 pb = __floats2bfloat162_rn(scv[jj][2], scv[jj][3]);
            uint2 st;
            st.x = *(unsigned int*)&pa;
            st.y = *(unsigned int*)&pb;
            *(uint2*)(Sc + sbase + (size_t)gj * 64 + rg * 4) = st;
#pragma unroll
            for (int a = 0; a < 4; a++) {
                float s = bf16r(scv[jj][a]) * 0.125f;
                int trow = qtile * 64 + rg * 4 + a;
                if (gj <= trow) mreg[a] = fmaxf(mreg[a], s);
            }
        }
    }

    // reduce max across the 8 kg lanes (fmaxf exact in any order)
#pragma unroll
    for (int a = 0; a < 4; a++) {
        float v = mreg[a];
        v = fmaxf(v, __shfl_xor_sync(0xffffffffu, v, 1));
        v = fmaxf(v, __shfl_xor_sync(0xffffffffu, v, 2));
        v = fmaxf(v, __shfl_xor_sync(0xffffffffu, v, 4));
        mreg[a] = v;
    }
    if (kg == 0) {
#pragma unroll
        for (int a = 0; a < 4; a++) m_s[rg * 4 + a] = mreg[a];
    }
    __syncthreads();

    // ================= pass 2: l chain (byte-identical structure to R10) =====
    {
        const int r2 = tid >> 1, hf2 = tid & 1;
        const unsigned pair_mask = 0x3u << ((tid & 31) & ~1);
        const float m = m_s[r2];
        float l = 0.0f;
        for (int kt = 0; kt <= qtile; kt++) {
            const int jmax = (kt == qtile) ? r2 : 63;
            int j = 0;
            for (; j + 1 <= jmax; j += 2) {
                int jm = j + hf2;
                float s = __bfloat162float(Sc[sbase + (size_t)(kt * 64 + jm) * 64 + r2]) * 0.125f;
                float e = exp_acc(s - m);
                float eo = __shfl_xor_sync(pair_mask, e, 1);
                float e_even = hf2 ? eo : e;
                float e_odd  = hf2 ? e  : eo;
                l += e_even;
                l += e_odd;
            }
            if (j <= jmax) {
                float s = __bfloat162float(Sc[sbase + (size_t)(kt * 64 + j) * 64 + r2]) * 0.125f;
                l += exp_acc(s - m);
            }
        }
        if (hf2 == 0) l_s[r2] = l;
    }
    __syncthreads();

    // ================= pass 3: probs + PV GEMM ===============================
    u64 o2[4][4];
#pragma unroll
    for (int a = 0; a < 4; a++)
#pragma unroll
        for (int b = 0; b < 4; b++) o2[a][b] = 0ull;

    const int pj = tid & 63, ph = tid >> 6;

    for (int kt = 0; kt <= qtile; kt++) {
        __syncthreads();   // protect prior tile's Ps/Vs reads
        // load V tile straight: Vs[j][dim]
        {
            const int key = tid >> 1, dh = tid & 1;
            const float* vp = Vc + (size_t)(kt * 64 + key) * (NKV * HD) + hk * HD + dh * 32;
#pragma unroll
            for (int u = 0; u < 8; u++)
                *(float4*)&KV[key][dh * 32 + u * 4] = ((const float4*)vp)[u];
        }
        // probs: thread owns column pj, rows ph*32..+31 -> Ps[row][pj]
        {
            const unsigned int* spw = (const unsigned int*)
                (Sc + sbase + (size_t)(kt * 64 + pj) * 64 + ph * 32);
            const int gj = kt * 64 + pj;
#pragma unroll
            for (int q4 = 0; q4 < 4; q4++) {
                uint4 wv = ((const uint4*)spw)[q4];
                unsigned int ws[4] = { wv.x, wv.y, wv.z, wv.w };
#pragma unroll
                for (int wi = 0; wi < 4; wi++) {
                    unsigned int word = ws[wi];
                    int rr0 = q4 * 8 + wi * 2;
#pragma unroll
                    for (int e = 0; e < 2; e++) {
                        int row = ph * 32 + rr0 + e;
                        float sv = __uint_as_float(e ? (word & 0xffff0000u)
                                                     : (word << 16));
                        float p = 0.0f;
                        if (gj <= qtile * 64 + row) {
                            float s = sv * 0.125f;
                            p = bf16r(__fdiv_rn(exp_acc(s - m_s[row]), l_s[row]));
                        }
                        QP[row][pj] = p;
                    }
                }
            }
        }
        __syncthreads();

        // PV: rows rg*4..+3, dims kg*8..+7, j ascending (zero-p adds exact)
#pragma unroll 2
        for (int j = 0; j < 64; j++) {
            float p0 = QP[rg * 4 + 0][j];
            float p1 = QP[rg * 4 + 1][j];
            float p2 = QP[rg * 4 + 2][j];
            float p3 = QP[rg * 4 + 3][j];
            u64 pp[4] = { pack2(p0, p0), pack2(p1, p1),
                          pack2(p2, p2), pack2(p3, p3) };
            double2 va = *(const double2*)&KV[j][kg * 8];
            double2 vb = *(const double2*)&KV[j][kg * 8 + 4];
            u64 vv[4] = { d2u(va.x), d2u(va.y), d2u(vb.x), d2u(vb.y) };
#pragma unroll
            for (int a = 0; a < 4; a++)
#pragma unroll
                for (int b = 0; b < 4; b++)
                    o2[a][b] = fma2(pp[a], vv[b], o2[a][b]);
        }
    }

    // epilogue: bf16-rounded outputs
#pragma unroll
    for (int a = 0; a < 4; a++) {
        int trow = qtile * 64 + rg * 4 + a;
        float* op = O + (size_t)trow * D_MODEL + h * HD + kg * 8;
        float f0, f1, f2, f3, f4, f5, f6, f7;
        unpack2(o2[a][0], f0, f1);
        unpack2(o2[a][1], f2, f3);
        unpack2(o2[a][2], f4, f5);
        unpack2(o2[a][3], f6, f7);
        *(float4*)&op[0] = make_float4(bf16r(f0), bf16r(f1), bf16r(f2), bf16r(f3));
        *(float4*)&op[4] = make_float4(bf16r(f4), bf16r(f5), bf16r(f6), bf16r(f7));
    }
}

// ---------------- host launcher ----------------------------------------------
extern "C" void kernel_launch(void* const* d_in, const int* in_sizes, int n_in,
                              void* d_out, int out_size) {
    (void)out_size;

    const float *x = 0, *w_o = 0, *scale_q = 0, *scale_kv = 0;
    const float *p524[2] = {0, 0}, *p262[3] = {0, 0, 0}, *p65[2] = {0, 0};
    int n524 = 0, n262 = 0, n65 = 0;
    for (int i = 0; i < n_in; i++) {
        switch (in_sizes[i]) {
            case 4194304: x = (const float*)d_in[i]; break;
            case 1048576: w_o = (const float*)d_in[i]; break;
            case 512:     scale_q  = (const float*)d_in[i]; break;
            case 256:     scale_kv = (const float*)d_in[i]; break;
            case 524288:  if (n524 < 2) p524[n524++] = (const float*)d_in[i]; break;
            case 262144:  if (n262 < 3) p262[n262++] = (const float*)d_in[i]; break;
            case 65536:   if (n65 < 2)  p65[n65++]  = (const float*)d_in[i]; break;
            default: break;
        }
    }
    const float* w_dq  = p524[0];
    const float* w_uq  = p524[1];
    const float* sin_p = p262[0];
    const float* cos_p = p262[1];
    const float* w_dkv = p262[2];
    const float* w_uk  = p65[0];
    const float* w_uv  = p65[1];
    float* out = (float*)d_out;

    float *qlat_raw, *qlat, *qb, *q_ro, *kvraw, *kvlat, *kb, *k_ro, *vb, *attn;
    __nv_bfloat16* scores;
    cudaGetSymbolAddress((void**)&qlat_raw, g_qlat_raw);
    cudaGetSymbolAddress((void**)&qlat,     g_qlat);
    cudaGetSymbolAddress((void**)&qb,       g_q);
    cudaGetSymbolAddress((void**)&q_ro,     g_q_ro);
    cudaGetSymbolAddress((void**)&kvraw,    g_kvraw);
    cudaGetSymbolAddress((void**)&kvlat,    g_kvlat);
    cudaGetSymbolAddress((void**)&kb,       g_k);
    cudaGetSymbolAddress((void**)&k_ro,     g_k_ro);
    cudaGetSymbolAddress((void**)&vb,       g_v);
    cudaGetSymbolAddress((void**)&attn,     g_attn);
    cudaGetSymbolAddress((void**)&scores,   g_scores);

    auto blocks = [](long long n) { return (int)((n + 255) / 256); };

    // q path
    gemm_ffma2<<<dim3(QL / 64, T_SEQ / 64), 128>>>(x, w_dq, qlat_raw,
                                                   T_SEQ, QL, D_MODEL);
    rmsnorm_kernel<<<T_SEQ, 256>>>(qlat_raw, scale_q, qlat, QL);
    gemm_ffma2<<<dim3((NH * HD) / 64, T_SEQ / 64), 128>>>(qlat, w_uq, qb,
                                                          T_SEQ, NH * HD, QL);

    // kv path
    gemm_ffma2<<<dim3(KVL / 64, T_SEQ / 64), 128>>>(x, w_dkv, kvraw,
                                                    T_SEQ, KVL, D_MODEL);
    rmsnorm_kernel<<<T_SEQ, 256>>>(kvraw, scale_kv, kvlat, KVL);
    gemm_ffma2<<<dim3((NKV * HD) / 64, T_SEQ / 64), 128>>>(kvlat, w_uk, kb,
                                                           T_SEQ, NKV * HD, KVL);
    gemm_ffma2<<<dim3((NKV * HD) / 64, T_SEQ / 64), 128>>>(kvlat, w_uv, vb,
                                                           T_SEQ, NKV * HD, KVL);

    // rope
    rope_kernel<<<blocks((long long)T_SEQ * NH * HD), 256>>>(qb, sin_p, cos_p, q_ro, NH);
    rope_kernel<<<blocks((long long)T_SEQ * NKV * HD), 256>>>(kb, sin_p, cos_p, k_ro, NKV);

    // attention
    attn_kernel<<<dim3(T_SEQ / 64, NH), 128>>>(q_ro, k_ro, vb, attn, scores);

    // final projection
    gemm_ffma2<<<dim3(D_MODEL / 64, T_SEQ / 64), 128>>>(attn, w_o, out,
                                                        T_SEQ, D_MODEL, D_MODEL);
}